// round 2
// baseline (speedup 1.0000x reference)
#include <cuda_runtime.h>
#include <math.h>

// ---------------------------------------------------------------------------
// Problem constants
// ---------------------------------------------------------------------------
#define BATCH 4
#define PIX   1024          // H*W = 32*32
#define BC    1024          // balanced channels
#define HEADS 8
#define HD    128           // head dim
#define TOTALC 3072
static const float ATT_SCALE = 0.08838834764831845f;  // 1/sqrt(128)

// ---------------------------------------------------------------------------
// Device scratch (allocation-free: __device__ globals)
// ---------------------------------------------------------------------------
__device__ float g_feat [3ull*BATCH*BC*PIX];   // normalized r,d,l        48MB
__device__ float g_cross[3ull*BATCH*BC*PIX];   // residual sums -> refs   48MB
__device__ float g_q   [(unsigned long long)BATCH*BC*PIX];  // 16MB
__device__ float g_k   [(unsigned long long)BATCH*BC*PIX];
__device__ float g_v   [(unsigned long long)BATCH*BC*PIX];
__device__ float g_att [(unsigned long long)BATCH*BC*PIX];
__device__ float g_spart[8ull*32*HD*HD];       // split-K partial scores  16MB
__device__ float g_attn [32ull*HD*HD];         // softmaxed attention      2MB
__device__ float g_part [3*8*4096*3];          // per-chunk {s,ss,zc}
__device__ float g_inv  [3*4096];              // 1/max(norm,eps) per (mod,b,p)
__device__ float g_metric[3*4096];             // var / zero-frac per (mod,b,p)
__device__ float g_pool [3*BATCH*BC];
__device__ float g_se   [3*BATCH*BC];          // SE sigmoid gates
__device__ float g_gates[3*4096];              // pixel gates per modality
__device__ float g_fused[(unsigned long long)BATCH*TOTALC*PIX];   // 48MB

// ---------------------------------------------------------------------------
// Generic tiled GEMM:  Y[z] (+)= A[z] @ X[z] + bias
//   A: [M,K] row-major (aStride==0 -> shared weights, else batched)
//   X: [K,P] row-major per batch (stride xStride)
//   Y: [M,P] row-major per batch (stride yStride)
// Tiles 128x128, K-step 8, 256 threads, 8x8 per thread.
// M,K,P must be multiples of 128/8/128 respectively (true for all call sites).
// ---------------------------------------------------------------------------
__global__ void __launch_bounds__(256) gemm128(
    const float* __restrict__ A, const float* __restrict__ X,
    const float* __restrict__ bias, float* __restrict__ Y,
    int M, int K, int P,
    long long aStride, long long xStride, long long yStride, int accum)
{
    const int z  = blockIdx.z;
    const float* Ab = A + (long long)z * aStride;
    const float* Xb = X + (long long)z * xStride;
    float*       Yb = Y + (long long)z * yStride;
    const int m0 = blockIdx.y * 128;
    const int p0 = blockIdx.x * 128;

    __shared__ float As[8][128];
    __shared__ float Bs[8][128];

    const int tid = threadIdx.x;
    const int tx = tid & 15;        // 0..15 -> P
    const int ty = tid >> 4;        // 0..15 -> M

    const int a_row = tid >> 1;           // 0..127
    const int a_k4  = (tid & 1) * 4;      // 0 or 4
    const int b_krow = tid >> 5;          // 0..7
    const int b_p4   = (tid & 31) * 4;    // 0..124

    float acc[8][8];
#pragma unroll
    for (int i = 0; i < 8; i++)
#pragma unroll
        for (int j = 0; j < 8; j++) acc[i][j] = 0.f;

    for (int k0 = 0; k0 < K; k0 += 8) {
        float4 av = *(const float4*)&Ab[(long long)(m0 + a_row) * K + k0 + a_k4];
        As[a_k4 + 0][a_row] = av.x;
        As[a_k4 + 1][a_row] = av.y;
        As[a_k4 + 2][a_row] = av.z;
        As[a_k4 + 3][a_row] = av.w;
        float4 bv = *(const float4*)&Xb[(long long)(k0 + b_krow) * P + p0 + b_p4];
        *(float4*)&Bs[b_krow][b_p4] = bv;
        __syncthreads();
#pragma unroll
        for (int kk = 0; kk < 8; kk++) {
            float ar[8], br[8];
            float4 a0 = *(const float4*)&As[kk][ty * 8];
            float4 a1 = *(const float4*)&As[kk][ty * 8 + 4];
            ar[0]=a0.x; ar[1]=a0.y; ar[2]=a0.z; ar[3]=a0.w;
            ar[4]=a1.x; ar[5]=a1.y; ar[6]=a1.z; ar[7]=a1.w;
            float4 b0 = *(const float4*)&Bs[kk][tx * 8];
            float4 b1 = *(const float4*)&Bs[kk][tx * 8 + 4];
            br[0]=b0.x; br[1]=b0.y; br[2]=b0.z; br[3]=b0.w;
            br[4]=b1.x; br[5]=b1.y; br[6]=b1.z; br[7]=b1.w;
#pragma unroll
            for (int i = 0; i < 8; i++)
#pragma unroll
                for (int j = 0; j < 8; j++)
                    acc[i][j] += ar[i] * br[j];
        }
        __syncthreads();
    }

#pragma unroll
    for (int i = 0; i < 8; i++) {
        const int m = m0 + ty * 8 + i;
        const float bval = bias ? bias[m] : 0.f;
#pragma unroll
        for (int j = 0; j < 8; j++) {
            long long idx = (long long)m * P + p0 + tx * 8 + j;
            float v = acc[i][j] + bval;
            if (accum) v += Yb[idx];
            Yb[idx] = v;
        }
    }
}

// ---------------------------------------------------------------------------
// Scores (NT GEMM, split-K over pixels): Spart[split,z] = Qh @ Kh^T (partial)
// grid (8 splits, 1, 32 heads*batch), block 256.
// ---------------------------------------------------------------------------
__global__ void __launch_bounds__(256) scores_nt(
    const float* __restrict__ Qg, const float* __restrict__ Kg,
    float* __restrict__ Spart)
{
    const int z = blockIdx.z;        // b*8+n
    const int split = blockIdx.x;    // 0..7, 128 pixels each
    const float* Qb = Qg + (long long)z * HD * PIX;
    const float* Kb = Kg + (long long)z * HD * PIX;

    __shared__ float Qs[16][128];
    __shared__ float Ks[16][128];

    const int tid = threadIdx.x;
    const int tx = tid & 15, ty = tid >> 4;
    const int r  = tid >> 1;            // channel row 0..127
    const int pq = (tid & 1) * 8;       // 0 or 8 within 16-wide k tile

    float acc[8][8];
#pragma unroll
    for (int i = 0; i < 8; i++)
#pragma unroll
        for (int j = 0; j < 8; j++) acc[i][j] = 0.f;

    for (int t = 0; t < 8; t++) {
        const int pb = split * 128 + t * 16;
        float4 q0 = *(const float4*)&Qb[(long long)r * PIX + pb + pq];
        float4 q1 = *(const float4*)&Qb[(long long)r * PIX + pb + pq + 4];
        Qs[pq+0][r]=q0.x; Qs[pq+1][r]=q0.y; Qs[pq+2][r]=q0.z; Qs[pq+3][r]=q0.w;
        Qs[pq+4][r]=q1.x; Qs[pq+5][r]=q1.y; Qs[pq+6][r]=q1.z; Qs[pq+7][r]=q1.w;
        float4 k0v = *(const float4*)&Kb[(long long)r * PIX + pb + pq];
        float4 k1v = *(const float4*)&Kb[(long long)r * PIX + pb + pq + 4];
        Ks[pq+0][r]=k0v.x; Ks[pq+1][r]=k0v.y; Ks[pq+2][r]=k0v.z; Ks[pq+3][r]=k0v.w;
        Ks[pq+4][r]=k1v.x; Ks[pq+5][r]=k1v.y; Ks[pq+6][r]=k1v.z; Ks[pq+7][r]=k1v.w;
        __syncthreads();
#pragma unroll
        for (int kk = 0; kk < 16; kk++) {
            float ar[8], br[8];
#pragma unroll
            for (int i = 0; i < 8; i++) ar[i] = Qs[kk][ty * 8 + i];
#pragma unroll
            for (int j = 0; j < 8; j++) br[j] = Ks[kk][tx * 8 + j];
#pragma unroll
            for (int i = 0; i < 8; i++)
#pragma unroll
                for (int j = 0; j < 8; j++)
                    acc[i][j] += ar[i] * br[j];
        }
        __syncthreads();
    }

    const long long base = (((long long)split * 32 + z) * HD) * HD;
#pragma unroll
    for (int i = 0; i < 8; i++)
#pragma unroll
        for (int j = 0; j < 8; j++)
            Spart[base + (long long)(ty * 8 + i) * HD + tx * 8 + j] = acc[i][j];
}

// ---------------------------------------------------------------------------
// Softmax over rows of 128, summing the 8 split-K partials first.
// grid (128 rows, 32 zh), block 128.
// ---------------------------------------------------------------------------
__global__ void softmax128(const float* __restrict__ Spart, float* __restrict__ attn)
{
    const int z = blockIdx.y;
    const int h = blockIdx.x;
    const int t = threadIdx.x;
    float s = 0.f;
#pragma unroll
    for (int sp = 0; sp < 8; sp++)
        s += Spart[(((long long)sp * 32 + z) * HD + h) * HD + t];
    s *= ATT_SCALE;

    __shared__ float red[128];
    red[t] = s; __syncthreads();
    for (int o = 64; o > 0; o >>= 1) {
        if (t < o) red[t] = fmaxf(red[t], red[t + o]);
        __syncthreads();
    }
    const float mx = red[0];
    __syncthreads();
    const float e = expf(s - mx);
    red[t] = e; __syncthreads();
    for (int o = 64; o > 0; o >>= 1) {
        if (t < o) red[t] += red[t + o];
        __syncthreads();
    }
    attn[((long long)z * HD + h) * HD + t] = e / red[0];
}

// ---------------------------------------------------------------------------
// Column-wise stats over raw projected features (pre-norm): s, ss, zero-count.
// Deterministic split over channels. grid (16 pix-blocks, 8 ch-chunks, 3 mods).
// ---------------------------------------------------------------------------
__global__ void colreduce(const float* __restrict__ feat, float* __restrict__ part)
{
    const int mod = blockIdx.z, cch = blockIdx.y;
    const int bp = blockIdx.x * 256 + threadIdx.x;   // 0..4095
    const int b = bp >> 10, p = bp & 1023;
    const float* base = feat + (((long long)(mod * BATCH + b) * BC + cch * 128) * PIX) + p;
    float s = 0.f, ss = 0.f, zc = 0.f;
    for (int c = 0; c < 128; c++) {
        float v = base[(long long)c * PIX];
        s += v; ss += v * v;
        zc += (v == 0.0f) ? 1.0f : 0.0f;
    }
    const long long o = (((long long)mod * 8 + cch) * 4096 + bp) * 3;
    part[o] = s; part[o + 1] = ss; part[o + 2] = zc;
}

__global__ void finalize_stats(const float* __restrict__ part,
                               float* __restrict__ inv, float* __restrict__ metric)
{
    const int mod = blockIdx.y;
    const int bp = blockIdx.x * 256 + threadIdx.x;
    float s = 0.f, ss = 0.f, zc = 0.f;
#pragma unroll
    for (int cch = 0; cch < 8; cch++) {
        const long long o = (((long long)mod * 8 + cch) * 4096 + bp) * 3;
        s += part[o]; ss += part[o + 1]; zc += part[o + 2];
    }
    const float norm = sqrtf(ss);
    const float m = fmaxf(norm, 1e-12f);
    const float iv = 1.0f / m;
    inv[mod * 4096 + bp] = iv;
    float met;
    if (mod == 0) {
        const float S = s * iv, SS = ss * iv * iv;
        met = (SS - S * S * (1.0f / 1024.0f)) * (1.0f / 1023.0f);
    } else {
        met = zc * (1.0f / 1024.0f);
    }
    metric[mod * 4096 + bp] = met;
}

// Normalize features in place and seed the residual (cross) buffer.
__global__ void normalize_copy(float* __restrict__ feat, float* __restrict__ cross,
                               const float* __restrict__ inv)
{
    const long long idx = (long long)blockIdx.x * 256 + threadIdx.x;
    const int p = idx & 1023;
    const int mb = (int)(idx >> 20);          // mod*4 + b
    const int mod = mb >> 2, b = mb & 3;
    const float v = feat[idx] * inv[mod * 4096 + b * 1024 + p];
    feat[idx] = v;
    cross[idx] = v;
}

// ---------------------------------------------------------------------------
// SE: pool over pixels, 2-layer MLP, apply
// ---------------------------------------------------------------------------
__global__ void se_pool(const float* __restrict__ cross, float* __restrict__ pool)
{
    const int c = blockIdx.x;          // channel
    const int mb = blockIdx.y;         // mod*4+b
    const float* base = cross + ((long long)mb * BC + c) * PIX;
    float s = 0.f;
    for (int p = threadIdx.x; p < PIX; p += 128) s += base[p];
    __shared__ float red[128];
    red[threadIdx.x] = s; __syncthreads();
    for (int o = 64; o > 0; o >>= 1) {
        if (threadIdx.x < o) red[threadIdx.x] += red[threadIdx.x + o];
        __syncthreads();
    }
    if (threadIdx.x == 0) pool[(long long)mb * BC + c] = red[0] * (1.0f / 1024.0f);
}

__global__ void se_mlp(const float* __restrict__ pool,
                       const float* __restrict__ w1, const float* __restrict__ b1,
                       const float* __restrict__ w2, const float* __restrict__ b2,
                       float* __restrict__ se)
{
    const int mb = blockIdx.x;          // mod*4+b
    const int mod = mb >> 2;
    const int tid = threadIdx.x;
    __shared__ float ps[1024];
    __shared__ float hh[64];
    for (int i = tid; i < 1024; i += 256) ps[i] = pool[(long long)mb * BC + i];
    __syncthreads();
    if (tid < 64) {
        float a = b1[mod * 64 + tid];
        const float* w = w1 + ((long long)mod * 64 + tid) * 1024;
        for (int c = 0; c < 1024; c++) a += w[c] * ps[c];
        hh[tid] = fmaxf(a, 0.f);
    }
    __syncthreads();
#pragma unroll
    for (int q = 0; q < 4; q++) {
        const int c = tid + q * 256;
        float a = b2[mod * 1024 + c];
        const float* w = w2 + ((long long)mod * 1024 + c) * 64;
#pragma unroll
        for (int j = 0; j < 64; j++) a += w[j] * hh[j];
        se[(long long)mb * BC + c] = 1.0f / (1.0f + expf(-a));
    }
}

__global__ void apply_se(float* __restrict__ cross, const float* __restrict__ se)
{
    const long long idx = (long long)blockIdx.x * 256 + threadIdx.x;
    const int c = (int)((idx >> 10) & 1023);
    const int mb = (int)(idx >> 20);
    cross[idx] *= se[(long long)mb * BC + c];
}

// ---------------------------------------------------------------------------
// Pixel gates: sigmoid(gate_w @ [refs, var, dsp, lsp] + gate_b)
// grid 16 blocks x 256 threads, thread per (b,p).
// ---------------------------------------------------------------------------
__global__ void gate_kernel(const float* __restrict__ refs,
                            const float* __restrict__ metric,
                            const float* __restrict__ gw, const float* __restrict__ gb,
                            float* __restrict__ gates)
{
    const int bp = blockIdx.x * 256 + threadIdx.x;
    const int b = bp >> 10, p = bp & 1023;
    float a0 = gb[0], a1 = gb[1], a2 = gb[2];
    for (int mod = 0; mod < 3; mod++) {
        const float* base = refs + ((long long)(mod * BATCH + b) * BC) * PIX + p;
        const float* w0 = gw + 0 * 3075 + mod * 1024;
        const float* w1 = gw + 1 * 3075 + mod * 1024;
        const float* w2 = gw + 2 * 3075 + mod * 1024;
        for (int c = 0; c < 1024; c++) {
            const float v = base[(long long)c * PIX];
            a0 += w0[c] * v; a1 += w1[c] * v; a2 += w2[c] * v;
        }
    }
#pragma unroll
    for (int mod = 0; mod < 3; mod++) {
        const float v = metric[mod * 4096 + bp];
        a0 += gw[0 * 3075 + 3072 + mod] * v;
        a1 += gw[1 * 3075 + 3072 + mod] * v;
        a2 += gw[2 * 3075 + 3072 + mod] * v;
    }
    gates[0 * 4096 + bp] = 1.0f / (1.0f + expf(-a0));
    gates[1 * 4096 + bp] = 1.0f / (1.0f + expf(-a1));
    gates[2 * 4096 + bp] = 1.0f / (1.0f + expf(-a2));
}

// Build fused input: fused[b, mod*1024+c, p] = ref * gate
__global__ void fuse_kernel(const float* __restrict__ refs,
                            const float* __restrict__ gates,
                            float* __restrict__ fused)
{
    const long long idx = (long long)blockIdx.x * 256 + threadIdx.x;
    const int p = idx & 1023;
    const int c = (int)((idx >> 10) & 1023);
    const int mb = (int)(idx >> 20);
    const int mod = mb >> 2, b = mb & 3;
    const float g = gates[mod * 4096 + b * 1024 + p];
    fused[(((long long)b * TOTALC + mod * 1024 + c) * PIX) + p] = refs[idx] * g;
}

// ---------------------------------------------------------------------------
// Host launcher
// ---------------------------------------------------------------------------
extern "C" void kernel_launch(void* const* d_in, const int* in_sizes, int n_in,
                              void* d_out, int out_size)
{
    const float* rgb      = (const float*)d_in[0];
    const float* depth    = (const float*)d_in[1];
    const float* lidar    = (const float*)d_in[2];
    const float* prw      = (const float*)d_in[3];
    const float* prb      = (const float*)d_in[4];
    const float* pdw      = (const float*)d_in[5];
    const float* pdb      = (const float*)d_in[6];
    const float* plw      = (const float*)d_in[7];
    const float* plb      = (const float*)d_in[8];
    const float* aqw      = (const float*)d_in[9];
    const float* aqb      = (const float*)d_in[10];
    const float* akw      = (const float*)d_in[11];
    const float* akb      = (const float*)d_in[12];
    const float* avw      = (const float*)d_in[13];
    const float* avb      = (const float*)d_in[14];
    const float* aow      = (const float*)d_in[15];
    const float* aob      = (const float*)d_in[16];
    const float* sew1     = (const float*)d_in[17];
    const float* seb1     = (const float*)d_in[18];
    const float* sew2     = (const float*)d_in[19];
    const float* seb2     = (const float*)d_in[20];
    const float* gw       = (const float*)d_in[21];
    const float* gb       = (const float*)d_in[22];
    const float* fw       = (const float*)d_in[23];
    const float* fb       = (const float*)d_in[24];
    float* out = (float*)d_out;

    float *feat, *cross, *q, *k, *v, *att, *spart, *attn, *part, *inv, *metric,
          *pool, *se, *gates, *fused;
    cudaGetSymbolAddress((void**)&feat,  g_feat);
    cudaGetSymbolAddress((void**)&cross, g_cross);
    cudaGetSymbolAddress((void**)&q,     g_q);
    cudaGetSymbolAddress((void**)&k,     g_k);
    cudaGetSymbolAddress((void**)&v,     g_v);
    cudaGetSymbolAddress((void**)&att,   g_att);
    cudaGetSymbolAddress((void**)&spart, g_spart);
    cudaGetSymbolAddress((void**)&attn,  g_attn);
    cudaGetSymbolAddress((void**)&part,  g_part);
    cudaGetSymbolAddress((void**)&inv,   g_inv);
    cudaGetSymbolAddress((void**)&metric,g_metric);
    cudaGetSymbolAddress((void**)&pool,  g_pool);
    cudaGetSymbolAddress((void**)&se,    g_se);
    cudaGetSymbolAddress((void**)&gates, g_gates);
    cudaGetSymbolAddress((void**)&fused, g_fused);

    const long long fmodStride = (long long)BATCH * BC * PIX;   // per-modality in feat/cross

    // --- 1. Projections (raw, pre-norm) ---
    gemm128<<<dim3(8, 8, BATCH), 256>>>(prw, rgb,   prb, feat + 0 * fmodStride,
        BC, 512, PIX, 0, 512LL * PIX, (long long)BC * PIX, 0);
    gemm128<<<dim3(8, 8, BATCH), 256>>>(pdw, depth, pdb, feat + 1 * fmodStride,
        BC, 256, PIX, 0, 256LL * PIX, (long long)BC * PIX, 0);
    gemm128<<<dim3(8, 8, BATCH), 256>>>(plw, lidar, plb, feat + 2 * fmodStride,
        BC, 64, PIX, 0, 64LL * PIX, (long long)BC * PIX, 0);

    // --- 2. Stats + normalization (+ seed cross with normalized features) ---
    colreduce<<<dim3(16, 8, 3), 256>>>(feat, part);
    finalize_stats<<<dim3(16, 3), 256>>>(part, inv, metric);
    normalize_copy<<<49152, 256>>>(feat, cross, inv);

    // --- 3. Six cross-attention blocks ---
    const int qmod[6] = {0, 0, 1, 1, 2, 2};
    const int kmod[6] = {1, 2, 0, 2, 0, 1};
    for (int i = 0; i < 6; i++) {
        const float* qf  = feat + (long long)qmod[i] * fmodStride;
        const float* kvf = feat + (long long)kmod[i] * fmodStride;
        const long long wOff = (long long)i * BC * BC;
        const long long bOff = (long long)i * BC;
        // Q, K, V projections
        gemm128<<<dim3(8, 8, BATCH), 256>>>(aqw + wOff, qf,  aqb + bOff, q,
            BC, BC, PIX, 0, (long long)BC * PIX, (long long)BC * PIX, 0);
        gemm128<<<dim3(8, 8, BATCH), 256>>>(akw + wOff, kvf, akb + bOff, k,
            BC, BC, PIX, 0, (long long)BC * PIX, (long long)BC * PIX, 0);
        gemm128<<<dim3(8, 8, BATCH), 256>>>(avw + wOff, kvf, avb + bOff, v,
            BC, BC, PIX, 0, (long long)BC * PIX, (long long)BC * PIX, 0);
        // scores (split-K) + softmax
        scores_nt<<<dim3(8, 1, 32), 256>>>(q, k, spart);
        softmax128<<<dim3(128, 32), 128>>>(spart, attn);
        // attn @ V  (batched A, one z per (b, head))
        gemm128<<<dim3(8, 1, 32), 256>>>(attn, v, nullptr, att,
            HD, HD, PIX, (long long)HD * HD, (long long)HD * PIX, (long long)HD * PIX, 0);
        // output projection, accumulate into cross[qmod]
        gemm128<<<dim3(8, 8, BATCH), 256>>>(aow + wOff, att, aob + bOff,
            cross + (long long)qmod[i] * fmodStride,
            BC, BC, PIX, 0, (long long)BC * PIX, (long long)BC * PIX, 1);
    }

    // --- 4. SE gating (cross -> refs in place) ---
    se_pool<<<dim3(1024, 12), 128>>>(cross, pool);
    se_mlp<<<12, 256>>>(pool, sew1, seb1, sew2, seb2, se);
    apply_se<<<49152, 256>>>(cross, se);

    // --- 5. Pixel gates ---
    gate_kernel<<<16, 256>>>(cross, metric, gw, gb, gates);

    // --- 6. Fused input + final fusion GEMM -> d_out ---
    fuse_kernel<<<49152, 256>>>(cross, gates, fused);
    gemm128<<<dim3(8, 24, BATCH), 256>>>(fw, fused, fb, out,
        TOTALC, TOTALC, PIX, 0, (long long)TOTALC * PIX, (long long)TOTALC * PIX, 0);
}

// round 7
// speedup vs baseline: 1.9864x; 1.9864x over previous
#include <cuda_runtime.h>
#include <cuda_bf16.h>
#include <cstdint>
#include <math.h>

static const float ATT_SCALE = 0.08838834764831845f;

// ---------------- scratch arena ----------------
__device__ __align__(1024) char g_arena[430ull << 20];

typedef __nv_bfloat16 bf16;

// ---------------- warp-MMA helper ----------------
__device__ __forceinline__ void mma16816(float* d, const uint32_t* a, const uint32_t* b) {
    asm volatile("mma.sync.aligned.m16n8k16.row.col.f32.bf16.bf16.f32 "
        "{%0,%1,%2,%3}, {%4,%5,%6,%7}, {%8,%9}, {%0,%1,%2,%3};"
        : "+f"(d[0]), "+f"(d[1]), "+f"(d[2]), "+f"(d[3])
        : "r"(a[0]), "r"(a[1]), "r"(a[2]), "r"(a[3]), "r"(b[0]), "r"(b[1]));
}

// ---------------- bf16x3 HMMA GEMM ----------------
// D[p,n] (+)= sum_k A[p,k]*B[n,k] + bias[n];  A batched, B shared.
// mode: 0 store, 1 accumulate into C, 2 transposed store C[n*ldc+p]
// grid (N/128, P/128, Z), block 256 (8 warps, 2x4), smem static.
#define SSTR 40   // smem row stride in bf16 (32 data + 8 pad) -> conflict-free frags
__global__ void __launch_bounds__(256) hmma_gemm(
    const bf16* __restrict__ Ahi, const bf16* __restrict__ Alo,
    long long aBatch, int lda,
    const bf16* __restrict__ Bhi, const bf16* __restrict__ Blo,
    const float* __restrict__ bias, float* __restrict__ C,
    long long cBatch, int ldc, int K, int mode)
{
    __shared__ bf16 sAh[128 * SSTR], sAl[128 * SSTR], sBh[128 * SSTR], sBl[128 * SSTR];
    const int tid = threadIdx.x, lane = tid & 31, warp = tid >> 5;
    const int wm = warp >> 2, wn = warp & 3;           // 2 x 4 warp grid
    const int gid = lane >> 2, tig = lane & 3;
    const int z = blockIdx.z;
    const int n0 = blockIdx.x * 128, p0 = blockIdx.y * 128;
    const uint4* Ah = (const uint4*)(Ahi + (long long)z * aBatch);
    const uint4* Al = (const uint4*)(Alo + (long long)z * aBatch);
    const uint4* Bh = (const uint4*)Bhi;
    const uint4* Bl = (const uint4*)Blo;
    const int lda8 = lda >> 3, K8 = K >> 3;
    const int NC = K >> 5;                              // 32-wide k chunks

    float acc[64];
#pragma unroll
    for (int i = 0; i < 64; i++) acc[i] = 0.f;

    // indices for gmem<->smem staging: idx in [0,512): row=idx>>2, c4=idx&3
    const int i0 = tid, i1 = tid + 256;
    const int r0s = i0 >> 2, c0s = i0 & 3, r1s = i1 >> 2, c1s = i1 & 3;

    uint4 pa0, pa1, pb0, pb1, pc0, pc1, pd0, pd1;
    {   // prefetch chunk 0
        pa0 = Ah[(long long)(p0 + r0s) * lda8 + c0s];
        pa1 = Ah[(long long)(p0 + r1s) * lda8 + c1s];
        pb0 = Al[(long long)(p0 + r0s) * lda8 + c0s];
        pb1 = Al[(long long)(p0 + r1s) * lda8 + c1s];
        pc0 = Bh[(long long)(n0 + r0s) * K8 + c0s];
        pc1 = Bh[(long long)(n0 + r1s) * K8 + c1s];
        pd0 = Bl[(long long)(n0 + r0s) * K8 + c0s];
        pd1 = Bl[(long long)(n0 + r1s) * K8 + c1s];
    }

    for (int c = 0; c < NC; c++) {
        // stage regs -> smem  (element offset: row*SSTR + c4*8)
        *(uint4*)&sAh[r0s * SSTR + c0s * 8] = pa0;
        *(uint4*)&sAh[r1s * SSTR + c1s * 8] = pa1;
        *(uint4*)&sAl[r0s * SSTR + c0s * 8] = pb0;
        *(uint4*)&sAl[r1s * SSTR + c1s * 8] = pb1;
        *(uint4*)&sBh[r0s * SSTR + c0s * 8] = pc0;
        *(uint4*)&sBh[r1s * SSTR + c1s * 8] = pc1;
        *(uint4*)&sBl[r0s * SSTR + c0s * 8] = pd0;
        *(uint4*)&sBl[r1s * SSTR + c1s * 8] = pd1;
        __syncthreads();

        if (c + 1 < NC) {   // prefetch next chunk
            const int kb = (c + 1) << 2;
            pa0 = Ah[(long long)(p0 + r0s) * lda8 + kb + c0s];
            pa1 = Ah[(long long)(p0 + r1s) * lda8 + kb + c1s];
            pb0 = Al[(long long)(p0 + r0s) * lda8 + kb + c0s];
            pb1 = Al[(long long)(p0 + r1s) * lda8 + kb + c1s];
            pc0 = Bh[(long long)(n0 + r0s) * K8 + kb + c0s];
            pc1 = Bh[(long long)(n0 + r1s) * K8 + kb + c1s];
            pd0 = Bl[(long long)(n0 + r0s) * K8 + kb + c0s];
            pd1 = Bl[(long long)(n0 + r1s) * K8 + kb + c1s];
        }

#pragma unroll
        for (int ks = 0; ks < 2; ks++) {
            const int k0 = ks * 16 + tig * 2;       // even
            // B fragments for this warp's 4 n-tiles (hi & lo)
            uint32_t bh[4][2], bl[4][2];
#pragma unroll
            for (int nt = 0; nt < 4; nt++) {
                const int n = wn * 32 + nt * 8 + gid;
                bh[nt][0] = *(const uint32_t*)&sBh[n * SSTR + k0];
                bh[nt][1] = *(const uint32_t*)&sBh[n * SSTR + k0 + 8];
                bl[nt][0] = *(const uint32_t*)&sBl[n * SSTR + k0];
                bl[nt][1] = *(const uint32_t*)&sBl[n * SSTR + k0 + 8];
            }
#pragma unroll
            for (int mt = 0; mt < 4; mt++) {
                const int r = wm * 64 + mt * 16 + gid;
                uint32_t ah[4], al[4];
                ah[0] = *(const uint32_t*)&sAh[r * SSTR + k0];
                ah[1] = *(const uint32_t*)&sAh[(r + 8) * SSTR + k0];
                ah[2] = *(const uint32_t*)&sAh[r * SSTR + k0 + 8];
                ah[3] = *(const uint32_t*)&sAh[(r + 8) * SSTR + k0 + 8];
                al[0] = *(const uint32_t*)&sAl[r * SSTR + k0];
                al[1] = *(const uint32_t*)&sAl[(r + 8) * SSTR + k0];
                al[2] = *(const uint32_t*)&sAl[r * SSTR + k0 + 8];
                al[3] = *(const uint32_t*)&sAl[(r + 8) * SSTR + k0 + 8];
#pragma unroll
                for (int nt = 0; nt < 4; nt++) {
                    float* d = &acc[(mt * 4 + nt) * 4];
                    mma16816(d, ah, bh[nt]);
                    mma16816(d, ah, bl[nt]);
                    mma16816(d, al, bh[nt]);
                }
            }
        }
        __syncthreads();
    }

    // epilogue
#pragma unroll
    for (int mt = 0; mt < 4; mt++) {
#pragma unroll
        for (int nt = 0; nt < 4; nt++) {
            const float* d = &acc[(mt * 4 + nt) * 4];
            const int r = p0 + wm * 64 + mt * 16 + gid;
            const int n = n0 + wn * 32 + nt * 8 + tig * 2;
            const float b0 = bias ? bias[n] : 0.f;
            const float b1 = bias ? bias[n + 1] : 0.f;
            if (mode == 2) {
                float* Cb = C + (long long)z * cBatch;
                Cb[(long long)n * ldc + r]           = d[0] + b0;
                Cb[(long long)(n + 1) * ldc + r]     = d[1] + b1;
                Cb[(long long)n * ldc + r + 8]       = d[2] + b0;
                Cb[(long long)(n + 1) * ldc + r + 8] = d[3] + b1;
            } else {
                float* c0p = C + (long long)z * cBatch + (long long)r * ldc + n;
                float* c1p = C + (long long)z * cBatch + (long long)(r + 8) * ldc + n;
                float2 v0 = make_float2(d[0] + b0, d[1] + b1);
                float2 v1 = make_float2(d[2] + b0, d[3] + b1);
                if (mode == 1) {
                    float2 o0 = *(float2*)c0p, o1 = *(float2*)c1p;
                    v0.x += o0.x; v0.y += o0.y; v1.x += o1.x; v1.y += o1.y;
                }
                *(float2*)c0p = v0;
                *(float2*)c1p = v1;
            }
        }
    }
}

// ---------------- fp32 projection GEMM: Y[b]=W@X[b]+bias ----------------
__global__ void __launch_bounds__(256) gemm128(
    const float* __restrict__ A, const float* __restrict__ X, const float* __restrict__ bias,
    float* __restrict__ Y, int K, long long xStride)
{
    const float* Xb = X + (long long)blockIdx.z * xStride;
    float* Yb = Y + (long long)blockIdx.z * 1048576;
    const int m0 = blockIdx.y * 128, p0 = blockIdx.x * 128;
    __shared__ float As[8][128], Bs[8][128];
    const int tid = threadIdx.x, tx = tid & 15, ty = tid >> 4;
    float acc[8][8];
#pragma unroll
    for (int i = 0; i < 8; i++)
#pragma unroll
        for (int j = 0; j < 8; j++) acc[i][j] = 0.f;
    for (int k0 = 0; k0 < K; k0 += 8) {
        const int ar = tid >> 1, ak = (tid & 1) * 4;
        float4 av = *(const float4*)&A[(long long)(m0 + ar) * K + k0 + ak];
        As[ak][ar] = av.x; As[ak+1][ar] = av.y; As[ak+2][ar] = av.z; As[ak+3][ar] = av.w;
        const int bk = tid >> 5, bp = (tid & 31) * 4;
        *(float4*)&Bs[bk][bp] = *(const float4*)&Xb[(long long)(k0 + bk) * 1024 + p0 + bp];
        __syncthreads();
#pragma unroll
        for (int kk = 0; kk < 8; kk++) {
            float ar8[8], br8[8];
            *(float4*)ar8     = *(float4*)&As[kk][ty*8]; *(float4*)(ar8+4) = *(float4*)&As[kk][ty*8+4];
            *(float4*)br8     = *(float4*)&Bs[kk][tx*8]; *(float4*)(br8+4) = *(float4*)&Bs[kk][tx*8+4];
#pragma unroll
            for (int i = 0; i < 8; i++)
#pragma unroll
                for (int j = 0; j < 8; j++) acc[i][j] += ar8[i] * br8[j];
        }
        __syncthreads();
    }
#pragma unroll
    for (int i = 0; i < 8; i++) {
        const float bv = bias[m0 + ty*8 + i];
#pragma unroll
        for (int j = 0; j < 8; j++)
            Yb[(long long)(m0 + ty*8 + i) * 1024 + p0 + tx*8 + j] = acc[i][j] + bv;
    }
}

// ---------------- stats on [mod][b][c][p] ----------------
__global__ void colreduce(const float* __restrict__ feat, float* __restrict__ part)
{
    const int mod = blockIdx.z, cch = blockIdx.y;
    const int bp = blockIdx.x * 256 + threadIdx.x;
    const float* base = feat + (((long long)(mod * 4 + (bp >> 10)) * 1024 + cch * 128) * 1024) + (bp & 1023);
    float s = 0.f, ss = 0.f, zc = 0.f;
    for (int c = 0; c < 128; c++) {
        float v = base[(long long)c * 1024];
        s += v; ss += v * v; zc += (v == 0.f) ? 1.f : 0.f;
    }
    const long long o = (((long long)mod * 8 + cch) * 4096 + bp) * 3;
    part[o] = s; part[o+1] = ss; part[o+2] = zc;
}
__global__ void finalize_stats(const float* __restrict__ part, float* __restrict__ inv, float* __restrict__ metric)
{
    const int mod = blockIdx.y, bp = blockIdx.x * 256 + threadIdx.x;
    float s = 0.f, ss = 0.f, zc = 0.f;
#pragma unroll
    for (int c = 0; c < 8; c++) {
        const long long o = (((long long)mod * 8 + c) * 4096 + bp) * 3;
        s += part[o]; ss += part[o+1]; zc += part[o+2];
    }
    const float iv = 1.f / fmaxf(sqrtf(ss), 1e-12f);
    inv[mod * 4096 + bp] = iv;
    float met;
    if (mod == 0) { const float S = s*iv, SS = ss*iv*iv; met = (SS - S*S*(1.f/1024.f)) * (1.f/1023.f); }
    else met = zc * (1.f/1024.f);
    metric[mod * 4096 + bp] = met;
}

// transpose [c][p]->[p][c], scale, emit fp32 + bf16 hi/lo
__global__ void trans_norm_split(const float* __restrict__ feat, const float* __restrict__ inv,
    float* __restrict__ crossT, bf16* __restrict__ fhi, bf16* __restrict__ flo)
{
    __shared__ float t[32][33];
    const int mb = blockIdx.z;
    const float* src = feat + (long long)mb * 1048576;
    const int c0 = blockIdx.y * 32, p0 = blockIdx.x * 32;
    const int tx = threadIdx.x & 31, ty = threadIdx.x >> 5;
    for (int r = ty; r < 32; r += 8) t[r][tx] = src[(long long)(c0 + r) * 1024 + p0 + tx];
    __syncthreads();
    for (int r = ty; r < 32; r += 8) {
        const int p = p0 + r, c = c0 + tx;
        const float v = t[tx][r] * inv[(mb >> 2) * 4096 + (mb & 3) * 1024 + p];
        const long long d = (long long)mb * 1048576 + (long long)p * 1024 + c;
        crossT[d] = v;
        const bf16 h = __float2bfloat16(v);
        fhi[d] = h;
        flo[d] = __float2bfloat16(v - __bfloat162float(h));
    }
}

__global__ void split_w(const float* __restrict__ src, bf16* __restrict__ hi, bf16* __restrict__ lo)
{
    const long long i = (long long)blockIdx.x * 256 + threadIdx.x;
    const float x = src[i];
    const bf16 h = __float2bfloat16(x);
    hi[i] = h; lo[i] = __float2bfloat16(x - __bfloat162float(h));
}

// ---------------- fp32 attention core ([b][p][c]) ----------------
__global__ void __launch_bounds__(256) scores_v2(const float* __restrict__ Q, const float* __restrict__ K, float* __restrict__ Sp)
{
    const int z = blockIdx.z, b = z >> 3, n = z & 7, split = blockIdx.x;
    const float* Qb = Q + (long long)b * 1048576 + n * 128;
    const float* Kb = K + (long long)b * 1048576 + n * 128;
    __shared__ float Qs[16][128], Ks[16][128];
    const int tid = threadIdx.x, tx = tid & 15, ty = tid >> 4;
    float acc[8][8];
#pragma unroll
    for (int i = 0; i < 8; i++)
#pragma unroll
        for (int j = 0; j < 8; j++) acc[i][j] = 0.f;
    for (int t = 0; t < 8; t++) {
        const int pb = split * 128 + t * 16;
#pragma unroll
        for (int j = 0; j < 2; j++) {
            const int idx = tid + j * 256, pr = idx >> 5, c4 = (idx & 31) * 4;
            *(float4*)&Qs[pr][c4] = *(const float4*)&Qb[(long long)(pb + pr) * 1024 + c4];
            *(float4*)&Ks[pr][c4] = *(const float4*)&Kb[(long long)(pb + pr) * 1024 + c4];
        }
        __syncthreads();
#pragma unroll
        for (int kk = 0; kk < 16; kk++) {
            float a8[8], b8[8];
            *(float4*)a8 = *(float4*)&Qs[kk][ty*8]; *(float4*)(a8+4) = *(float4*)&Qs[kk][ty*8+4];
            *(float4*)b8 = *(float4*)&Ks[kk][tx*8]; *(float4*)(b8+4) = *(float4*)&Ks[kk][tx*8+4];
#pragma unroll
            for (int i = 0; i < 8; i++)
#pragma unroll
                for (int j = 0; j < 8; j++) acc[i][j] += a8[i] * b8[j];
        }
        __syncthreads();
    }
    const long long base = ((long long)split * 32 + z) * 16384;
#pragma unroll
    for (int i = 0; i < 8; i++)
#pragma unroll
        for (int j = 0; j < 8; j++)
            Sp[base + (long long)(ty*8+i) * 128 + tx*8 + j] = acc[i][j];
}

__global__ void softmax_v2(const float* __restrict__ Sp, float* __restrict__ attnT)
{
    const int z = blockIdx.y, h = blockIdx.x, t = threadIdx.x;
    float s = 0.f;
#pragma unroll
    for (int sp = 0; sp < 8; sp++) s += Sp[((long long)sp * 32 + z) * 16384 + h * 128 + t];
    s *= ATT_SCALE;
    __shared__ float red[128];
    red[t] = s; __syncthreads();
    for (int o = 64; o > 0; o >>= 1) { if (t < o) red[t] = fmaxf(red[t], red[t+o]); __syncthreads(); }
    const float mx = red[0]; __syncthreads();
    const float e = expf(s - mx);
    red[t] = e; __syncthreads();
    for (int o = 64; o > 0; o >>= 1) { if (t < o) red[t] += red[t+o]; __syncthreads(); }
    attnT[(long long)z * 16384 + t * 128 + h] = e / red[0];
}

__global__ void __launch_bounds__(256) av_v2(const float* __restrict__ V, const float* __restrict__ attnT,
    bf16* __restrict__ Oh, bf16* __restrict__ Ol)
{
    const int z = blockIdx.z, b = z >> 3, n = z & 7, p0 = blockIdx.x * 128;
    const float* Vb = V + (long long)b * 1048576 + n * 128;
    const float* At = attnT + (long long)z * 16384;
    __shared__ float As[8][128], Bs[8][128];
    const int tid = threadIdx.x, tx = tid & 15, ty = tid >> 4;
    float acc[8][8];
#pragma unroll
    for (int i = 0; i < 8; i++)
#pragma unroll
        for (int j = 0; j < 8; j++) acc[i][j] = 0.f;
    for (int k0 = 0; k0 < 128; k0 += 8) {
        const int row = tid >> 1, k4 = (tid & 1) * 4;
        float4 av = *(const float4*)&Vb[(long long)(p0 + row) * 1024 + k0 + k4];
        As[k4][row] = av.x; As[k4+1][row] = av.y; As[k4+2][row] = av.z; As[k4+3][row] = av.w;
        const int kr = tid >> 5, i4 = (tid & 31) * 4;
        *(float4*)&Bs[kr][i4] = *(const float4*)&At[(k0 + kr) * 128 + i4];
        __syncthreads();
#pragma unroll
        for (int kk = 0; kk < 8; kk++) {
            float a8[8], b8[8];
            *(float4*)a8 = *(float4*)&As[kk][ty*8]; *(float4*)(a8+4) = *(float4*)&As[kk][ty*8+4];
            *(float4*)b8 = *(float4*)&Bs[kk][tx*8]; *(float4*)(b8+4) = *(float4*)&Bs[kk][tx*8+4];
#pragma unroll
            for (int i = 0; i < 8; i++)
#pragma unroll
                for (int j = 0; j < 8; j++) acc[i][j] += a8[i] * b8[j];
        }
        __syncthreads();
    }
    const long long ob = (long long)b * 1048576 + n * 128;
#pragma unroll
    for (int i = 0; i < 8; i++)
#pragma unroll
        for (int j = 0; j < 8; j++) {
            const float x = acc[i][j];
            const bf16 h = __float2bfloat16(x);
            const long long d = ob + (long long)(p0 + ty*8 + i) * 1024 + tx*8 + j;
            Oh[d] = h; Ol[d] = __float2bfloat16(x - __bfloat162float(h));
        }
}

// ---------------- SE / gates / fuse ([p][c]) ----------------
__global__ void se_pool_v2(const float* __restrict__ crossT, float* __restrict__ pool)
{
    const int mb = blockIdx.y, c = blockIdx.x * 128 + threadIdx.x;
    const float* base = crossT + (long long)mb * 1048576 + c;
    float s = 0.f;
#pragma unroll 4
    for (int p = 0; p < 1024; p++) s += base[(long long)p * 1024];
    pool[mb * 1024 + c] = s * (1.f / 1024.f);
}
__global__ void se_mlp(const float* __restrict__ pool,
    const float* __restrict__ w1, const float* __restrict__ b1,
    const float* __restrict__ w2, const float* __restrict__ b2, float* __restrict__ se)
{
    const int mb = blockIdx.x, mod = mb >> 2, tid = threadIdx.x;
    __shared__ float ps[1024], hh[64];
    for (int i = tid; i < 1024; i += 256) ps[i] = pool[mb * 1024 + i];
    __syncthreads();
    if (tid < 64) {
        float a = b1[mod * 64 + tid];
        const float* w = w1 + ((long long)mod * 64 + tid) * 1024;
        for (int c = 0; c < 1024; c++) a += w[c] * ps[c];
        hh[tid] = fmaxf(a, 0.f);
    }
    __syncthreads();
#pragma unroll
    for (int q = 0; q < 4; q++) {
        const int c = tid + q * 256;
        float a = b2[mod * 1024 + c];
        const float* w = w2 + ((long long)mod * 1024 + c) * 64;
#pragma unroll
        for (int j = 0; j < 64; j++) a += w[j] * hh[j];
        se[mb * 1024 + c] = 1.f / (1.f + expf(-a));
    }
}
__global__ void apply_se(float* __restrict__ crossT, const float* __restrict__ se)
{
    const long long idx = (long long)blockIdx.x * 256 + threadIdx.x;
    crossT[idx] *= se[(int)(idx >> 20) * 1024 + (int)(idx & 1023)];
}

__global__ void __launch_bounds__(128) gate_v2(const float* __restrict__ crossT,
    const float* __restrict__ metric, const float* __restrict__ gw, const float* __restrict__ gb,
    float* __restrict__ gates)
{
    const int bp = blockIdx.x, b = bp >> 10, p = bp & 1023, t = threadIdx.x;
    float a0 = 0.f, a1 = 0.f, a2 = 0.f;
    for (int mod = 0; mod < 3; mod++) {
        const float* base = crossT + ((long long)(mod * 4 + b) * 1024 + p) * 1024;
        for (int c = t; c < 1024; c += 128) {
            const float v = base[c];
            a0 += gw[0*3075 + mod*1024 + c] * v;
            a1 += gw[1*3075 + mod*1024 + c] * v;
            a2 += gw[2*3075 + mod*1024 + c] * v;
        }
    }
    for (int o = 16; o > 0; o >>= 1) {
        a0 += __shfl_xor_sync(0xFFFFFFFF, a0, o);
        a1 += __shfl_xor_sync(0xFFFFFFFF, a1, o);
        a2 += __shfl_xor_sync(0xFFFFFFFF, a2, o);
    }
    __shared__ float r[4][3];
    if ((t & 31) == 0) { r[t>>5][0] = a0; r[t>>5][1] = a1; r[t>>5][2] = a2; }
    __syncthreads();
    if (t == 0) {
        float s0 = gb[0], s1 = gb[1], s2 = gb[2];
        for (int i = 0; i < 4; i++) { s0 += r[i][0]; s1 += r[i][1]; s2 += r[i][2]; }
        for (int mod = 0; mod < 3; mod++) {
            const float m = metric[mod * 4096 + bp];
            s0 += gw[0*3075 + 3072 + mod] * m;
            s1 += gw[1*3075 + 3072 + mod] * m;
            s2 += gw[2*3075 + 3072 + mod] * m;
        }
        gates[0*4096 + bp] = 1.f/(1.f+expf(-s0));
        gates[1*4096 + bp] = 1.f/(1.f+expf(-s1));
        gates[2*4096 + bp] = 1.f/(1.f+expf(-s2));
    }
}

__global__ void fuse_conv(const float* __restrict__ crossT, const float* __restrict__ gates,
    bf16* __restrict__ fhi, bf16* __restrict__ flo)
{
    const long long idx = (long long)blockIdx.x * 256 + threadIdx.x;
    const int c = (int)(idx & 1023);
    const long long rr = idx >> 10;
    const int p = (int)(rr & 1023), mb = (int)(rr >> 10), mod = mb >> 2, b = mb & 3;
    const float x = crossT[idx] * gates[mod * 4096 + b * 1024 + p];
    const long long d = ((long long)b * 1024 + p) * 3072 + mod * 1024 + c;
    const bf16 h = __float2bfloat16(x);
    fhi[d] = h; flo[d] = __float2bfloat16(x - __bfloat162float(h));
}

// ---------------- host ----------------
extern "C" void kernel_launch(void* const* d_in, const int* in_sizes, int n_in,
                              void* d_out, int out_size)
{
    const float *rgb=(const float*)d_in[0], *depth=(const float*)d_in[1], *lidar=(const float*)d_in[2];
    const float *prw=(const float*)d_in[3], *prb=(const float*)d_in[4], *pdw=(const float*)d_in[5], *pdb=(const float*)d_in[6];
    const float *plw=(const float*)d_in[7], *plb=(const float*)d_in[8];
    const float *aqw=(const float*)d_in[9], *aqb=(const float*)d_in[10], *akw=(const float*)d_in[11], *akb=(const float*)d_in[12];
    const float *avw=(const float*)d_in[13], *avb=(const float*)d_in[14], *aow=(const float*)d_in[15], *aob=(const float*)d_in[16];
    const float *sew1=(const float*)d_in[17], *seb1=(const float*)d_in[18], *sew2=(const float*)d_in[19], *seb2=(const float*)d_in[20];
    const float *gw=(const float*)d_in[21], *gb=(const float*)d_in[22], *fw=(const float*)d_in[23], *fb=(const float*)d_in[24];
    float* out = (float*)d_out;

    char* A = nullptr;
    cudaGetSymbolAddress((void**)&A, g_arena);
    size_t o = 0;
    auto al = [&](size_t bytes) { char* p = A + o; o += (bytes + 1023) & ~(size_t)1023; return p; };
    float* feat   = (float*)al(50331648);
    float* crossT = (float*)al(50331648);
    float* q      = (float*)al(16777216);
    float* k      = (float*)al(16777216);
    float* v      = (float*)al(16777216);
    float* spart  = (float*)al(16777216);
    float* attnT  = (float*)al(2097152);
    float* part   = (float*)al(1179648);
    float* inv    = (float*)al(49152);
    float* metric = (float*)al(49152);
    float* pool   = (float*)al(49152);
    float* se     = (float*)al(49152);
    float* gates  = (float*)al(49152);
    bf16* f_hi  = (bf16*)al(25165824);
    bf16* f_lo  = (bf16*)al(25165824);
    bf16* at_hi = (bf16*)al(8388608);
    bf16* at_lo = (bf16*)al(8388608);
    bf16* fu_hi = (bf16*)al(25165824);
    bf16* fu_lo = (bf16*)al(25165824);
    bf16* wq_hi = (bf16*)al(12582912); bf16* wq_lo = (bf16*)al(12582912);
    bf16* wk_hi = (bf16*)al(12582912); bf16* wk_lo = (bf16*)al(12582912);
    bf16* wv_hi = (bf16*)al(12582912); bf16* wv_lo = (bf16*)al(12582912);
    bf16* wo_hi = (bf16*)al(12582912); bf16* wo_lo = (bf16*)al(12582912);
    bf16* wf_hi = (bf16*)al(18874368); bf16* wf_lo = (bf16*)al(18874368);

    split_w<<<24576, 256>>>(aqw, wq_hi, wq_lo);
    split_w<<<24576, 256>>>(akw, wk_hi, wk_lo);
    split_w<<<24576, 256>>>(avw, wv_hi, wv_lo);
    split_w<<<24576, 256>>>(aow, wo_hi, wo_lo);
    split_w<<<36864, 256>>>(fw,  wf_hi, wf_lo);

    gemm128<<<dim3(8,8,4), 256>>>(prw, rgb,   prb, feat,            512, 524288);
    gemm128<<<dim3(8,8,4), 256>>>(pdw, depth, pdb, feat + 4194304,  256, 262144);
    gemm128<<<dim3(8,8,4), 256>>>(plw, lidar, plb, feat + 8388608,   64, 65536);

    colreduce<<<dim3(16,8,3), 256>>>(feat, part);
    finalize_stats<<<dim3(16,3), 256>>>(part, inv, metric);
    trans_norm_split<<<dim3(32,32,12), 256>>>(feat, inv, crossT, f_hi, f_lo);

    const int qmod[6] = {0,0,1,1,2,2}, kmod[6] = {1,2,0,2,0,1};
    for (int i = 0; i < 6; i++) {
        const long long qo = (long long)qmod[i] * 4194304, ko = (long long)kmod[i] * 4194304;
        const long long wOff = (long long)i * 1048576;
        hmma_gemm<<<dim3(8,8,4), 256>>>(f_hi+qo, f_lo+qo, 1048576, 1024,
            wq_hi+wOff, wq_lo+wOff, aqb+i*1024, q, 1048576, 1024, 1024, 0);
        hmma_gemm<<<dim3(8,8,4), 256>>>(f_hi+ko, f_lo+ko, 1048576, 1024,
            wk_hi+wOff, wk_lo+wOff, akb+i*1024, k, 1048576, 1024, 1024, 0);
        hmma_gemm<<<dim3(8,8,4), 256>>>(f_hi+ko, f_lo+ko, 1048576, 1024,
            wv_hi+wOff, wv_lo+wOff, avb+i*1024, v, 1048576, 1024, 1024, 0);
        scores_v2<<<dim3(8,1,32), 256>>>(q, k, spart);
        softmax_v2<<<dim3(128,32), 128>>>(spart, attnT);
        av_v2<<<dim3(8,1,32), 256>>>(v, attnT, at_hi, at_lo);
        hmma_gemm<<<dim3(8,8,4), 256>>>(at_hi, at_lo, 1048576, 1024,
            wo_hi+wOff, wo_lo+wOff, aob+i*1024, crossT + qmod[i]*4194304, 1048576, 1024, 1024, 1);
    }

    se_pool_v2<<<dim3(8,12), 128>>>(crossT, pool);
    se_mlp<<<12, 256>>>(pool, sew1, seb1, sew2, seb2, se);
    apply_se<<<49152, 256>>>(crossT, se);
    gate_v2<<<4096, 128>>>(crossT, metric, gw, gb, gates);
    fuse_conv<<<49152, 256>>>(crossT, gates, fu_hi, fu_lo);
    hmma_gemm<<<dim3(24,8,4), 256>>>(fu_hi, fu_lo, 3145728, 3072,
        wf_hi, wf_lo, fb, out, 3145728, 1024, 3072, 2);
}

// round 8
// speedup vs baseline: 2.0869x; 1.0506x over previous
#include <cuda_runtime.h>
#include <cuda_bf16.h>
#include <cstdint>
#include <math.h>

static const float ATT_SCALE = 0.08838834764831845f;

// ---------------- scratch arena ----------------
__device__ __align__(1024) char g_arena[430ull << 20];

typedef __nv_bfloat16 bf16;

// ---------------- warp-MMA helper ----------------
__device__ __forceinline__ void mma16816(float* d, const uint32_t* a, const uint32_t* b) {
    asm volatile("mma.sync.aligned.m16n8k16.row.col.f32.bf16.bf16.f32 "
        "{%0,%1,%2,%3}, {%4,%5,%6,%7}, {%8,%9}, {%0,%1,%2,%3};"
        : "+f"(d[0]), "+f"(d[1]), "+f"(d[2]), "+f"(d[3])
        : "r"(a[0]), "r"(a[1]), "r"(a[2]), "r"(a[3]), "r"(b[0]), "r"(b[1]));
}
__device__ __forceinline__ uint32_t smem_u32(const void* p) {
    uint32_t a; asm("{ .reg .u64 t; cvta.to.shared.u64 t, %1; cvt.u32.u64 %0, t; }" : "=r"(a) : "l"(p)); return a;
}
#define CPA(dst, src) asm volatile("cp.async.cg.shared.global [%0], [%1], 16;" :: "r"(dst), "l"(src))
#define CP_COMMIT()   asm volatile("cp.async.commit_group;")
#define CP_WAIT1()    asm volatile("cp.async.wait_group 1;")
#define CP_WAIT0()    asm volatile("cp.async.wait_group 0;")

// ---------------- bf16x3 HMMA GEMM, cp.async double-buffered ----------------
// D[p,n] (+)= sum_k A[p,k]*B[n,k] + bias[n];  A batched, B shared.
// mode: 0 store, 1 accumulate into C, 2 transposed store C[n*ldc+p]
// grid (N/128, P/128, Z), block 256 (8 warps, 2x4), dyn smem 81920B.
#define SSTR 40                 // smem row stride in bf16 (80B, 16B-aligned)
#define ARR  5120               // elems per array (128*40)
#define STG  20480              // elems per stage (4 arrays)
#define HG_SMEM 81920
__global__ void __launch_bounds__(256) hmma_gemm(
    const bf16* __restrict__ Ahi, const bf16* __restrict__ Alo,
    long long aBatch, int lda,
    const bf16* __restrict__ Bhi, const bf16* __restrict__ Blo,
    const float* __restrict__ bias, float* __restrict__ C,
    long long cBatch, int ldc, int K, int mode)
{
    extern __shared__ bf16 sm[];
    const uint32_t smb = smem_u32(sm);
    const int tid = threadIdx.x, lane = tid & 31, warp = tid >> 5;
    const int wm = warp >> 2, wn = warp & 3;
    const int gid = lane >> 2, tig = lane & 3;
    const int z = blockIdx.z;
    const int n0 = blockIdx.x * 128, p0 = blockIdx.y * 128;
    const uint4* Ah = (const uint4*)(Ahi + (long long)z * aBatch);
    const uint4* Al = (const uint4*)(Alo + (long long)z * aBatch);
    const uint4* Bh = (const uint4*)Bhi;
    const uint4* Bl = (const uint4*)Blo;
    const int lda8 = lda >> 3, K8 = K >> 3;
    const int NC = K >> 5;

    // staging: 512 16B-chunks per array; thread covers rows r0, r0+64, col c0
    const int r0 = tid >> 2, c0 = tid & 3;
    const uint32_t dOff0 = (uint32_t)((r0 * SSTR + c0 * 8) * 2);
    const uint32_t dOff1 = (uint32_t)(((r0 + 64) * SSTR + c0 * 8) * 2);

    float acc[64];
#pragma unroll
    for (int i = 0; i < 64; i++) acc[i] = 0.f;

#define ISSUE(cc, ss) do { \
        const int kb = (cc) << 2; \
        const uint32_t sb_ = smb + (ss) * (STG * 2); \
        CPA(sb_ + dOff0,            Ah + (long long)(p0 + r0) * lda8 + kb + c0); \
        CPA(sb_ + dOff1,            Ah + (long long)(p0 + r0 + 64) * lda8 + kb + c0); \
        CPA(sb_ + ARR*2 + dOff0,    Al + (long long)(p0 + r0) * lda8 + kb + c0); \
        CPA(sb_ + ARR*2 + dOff1,    Al + (long long)(p0 + r0 + 64) * lda8 + kb + c0); \
        CPA(sb_ + ARR*4 + dOff0,    Bh + (long long)(n0 + r0) * K8 + kb + c0); \
        CPA(sb_ + ARR*4 + dOff1,    Bh + (long long)(n0 + r0 + 64) * K8 + kb + c0); \
        CPA(sb_ + ARR*6 + dOff0,    Bl + (long long)(n0 + r0) * K8 + kb + c0); \
        CPA(sb_ + ARR*6 + dOff1,    Bl + (long long)(n0 + r0 + 64) * K8 + kb + c0); \
        CP_COMMIT(); \
    } while (0)

    ISSUE(0, 0);
    for (int c = 0; c < NC; c++) {
        if (c + 1 < NC) { ISSUE(c + 1, (c + 1) & 1); CP_WAIT1(); }
        else            { CP_WAIT0(); }
        __syncthreads();
        const bf16* st = sm + (c & 1) * STG;
        const bf16* sAh = st, *sAl = st + ARR, *sBh = st + 2 * ARR, *sBl = st + 3 * ARR;
#pragma unroll
        for (int ks = 0; ks < 2; ks++) {
            const int k0 = ks * 16 + tig * 2;
            uint32_t bh[4][2], bl[4][2];
#pragma unroll
            for (int nt = 0; nt < 4; nt++) {
                const int n = wn * 32 + nt * 8 + gid;
                bh[nt][0] = *(const uint32_t*)&sBh[n * SSTR + k0];
                bh[nt][1] = *(const uint32_t*)&sBh[n * SSTR + k0 + 8];
                bl[nt][0] = *(const uint32_t*)&sBl[n * SSTR + k0];
                bl[nt][1] = *(const uint32_t*)&sBl[n * SSTR + k0 + 8];
            }
#pragma unroll
            for (int mt = 0; mt < 4; mt++) {
                const int r = wm * 64 + mt * 16 + gid;
                uint32_t ah[4], al[4];
                ah[0] = *(const uint32_t*)&sAh[r * SSTR + k0];
                ah[1] = *(const uint32_t*)&sAh[(r + 8) * SSTR + k0];
                ah[2] = *(const uint32_t*)&sAh[r * SSTR + k0 + 8];
                ah[3] = *(const uint32_t*)&sAh[(r + 8) * SSTR + k0 + 8];
                al[0] = *(const uint32_t*)&sAl[r * SSTR + k0];
                al[1] = *(const uint32_t*)&sAl[(r + 8) * SSTR + k0];
                al[2] = *(const uint32_t*)&sAl[r * SSTR + k0 + 8];
                al[3] = *(const uint32_t*)&sAl[(r + 8) * SSTR + k0 + 8];
#pragma unroll
                for (int nt = 0; nt < 4; nt++) {
                    float* d = &acc[(mt * 4 + nt) * 4];
                    mma16816(d, ah, bh[nt]);
                    mma16816(d, ah, bl[nt]);
                    mma16816(d, al, bh[nt]);
                }
            }
        }
        __syncthreads();
    }
#undef ISSUE

    // epilogue
#pragma unroll
    for (int mt = 0; mt < 4; mt++) {
#pragma unroll
        for (int nt = 0; nt < 4; nt++) {
            const float* d = &acc[(mt * 4 + nt) * 4];
            const int r = p0 + wm * 64 + mt * 16 + gid;
            const int n = n0 + wn * 32 + nt * 8 + tig * 2;
            const float b0 = bias ? bias[n] : 0.f;
            const float b1 = bias ? bias[n + 1] : 0.f;
            if (mode == 2) {
                float* Cb = C + (long long)z * cBatch;
                Cb[(long long)n * ldc + r]           = d[0] + b0;
                Cb[(long long)(n + 1) * ldc + r]     = d[1] + b1;
                Cb[(long long)n * ldc + r + 8]       = d[2] + b0;
                Cb[(long long)(n + 1) * ldc + r + 8] = d[3] + b1;
            } else {
                float* c0p = C + (long long)z * cBatch + (long long)r * ldc + n;
                float* c1p = C + (long long)z * cBatch + (long long)(r + 8) * ldc + n;
                float2 v0 = make_float2(d[0] + b0, d[1] + b1);
                float2 v1 = make_float2(d[2] + b0, d[3] + b1);
                if (mode == 1) {
                    float2 o0 = *(float2*)c0p, o1 = *(float2*)c1p;
                    v0.x += o0.x; v0.y += o0.y; v1.x += o1.x; v1.y += o1.y;
                }
                *(float2*)c0p = v0;
                *(float2*)c1p = v1;
            }
        }
    }
}

// ---------------- fp32 projection GEMM: Y[b]=W@X[b]+bias ----------------
__global__ void __launch_bounds__(256) gemm128(
    const float* __restrict__ A, const float* __restrict__ X, const float* __restrict__ bias,
    float* __restrict__ Y, int K, long long xStride)
{
    const float* Xb = X + (long long)blockIdx.z * xStride;
    float* Yb = Y + (long long)blockIdx.z * 1048576;
    const int m0 = blockIdx.y * 128, p0 = blockIdx.x * 128;
    __shared__ float As[8][128], Bs[8][128];
    const int tid = threadIdx.x, tx = tid & 15, ty = tid >> 4;
    float acc[8][8];
#pragma unroll
    for (int i = 0; i < 8; i++)
#pragma unroll
        for (int j = 0; j < 8; j++) acc[i][j] = 0.f;
    for (int k0 = 0; k0 < K; k0 += 8) {
        const int ar = tid >> 1, ak = (tid & 1) * 4;
        float4 av = *(const float4*)&A[(long long)(m0 + ar) * K + k0 + ak];
        As[ak][ar] = av.x; As[ak+1][ar] = av.y; As[ak+2][ar] = av.z; As[ak+3][ar] = av.w;
        const int bk = tid >> 5, bp = (tid & 31) * 4;
        *(float4*)&Bs[bk][bp] = *(const float4*)&Xb[(long long)(k0 + bk) * 1024 + p0 + bp];
        __syncthreads();
#pragma unroll
        for (int kk = 0; kk < 8; kk++) {
            float ar8[8], br8[8];
            *(float4*)ar8     = *(float4*)&As[kk][ty*8]; *(float4*)(ar8+4) = *(float4*)&As[kk][ty*8+4];
            *(float4*)br8     = *(float4*)&Bs[kk][tx*8]; *(float4*)(br8+4) = *(float4*)&Bs[kk][tx*8+4];
#pragma unroll
            for (int i = 0; i < 8; i++)
#pragma unroll
                for (int j = 0; j < 8; j++) acc[i][j] += ar8[i] * br8[j];
        }
        __syncthreads();
    }
#pragma unroll
    for (int i = 0; i < 8; i++) {
        const float bv = bias[m0 + ty*8 + i];
#pragma unroll
        for (int j = 0; j < 8; j++)
            Yb[(long long)(m0 + ty*8 + i) * 1024 + p0 + tx*8 + j] = acc[i][j] + bv;
    }
}

// ---------------- stats on [mod][b][c][p] ----------------
__global__ void colreduce(const float* __restrict__ feat, float* __restrict__ part)
{
    const int mod = blockIdx.z, cch = blockIdx.y;
    const int bp = blockIdx.x * 256 + threadIdx.x;
    const float* base = feat + (((long long)(mod * 4 + (bp >> 10)) * 1024 + cch * 128) * 1024) + (bp & 1023);
    float s = 0.f, ss = 0.f, zc = 0.f;
    for (int c = 0; c < 128; c++) {
        float v = base[(long long)c * 1024];
        s += v; ss += v * v; zc += (v == 0.f) ? 1.f : 0.f;
    }
    const long long o = (((long long)mod * 8 + cch) * 4096 + bp) * 3;
    part[o] = s; part[o+1] = ss; part[o+2] = zc;
}
__global__ void finalize_stats(const float* __restrict__ part, float* __restrict__ inv, float* __restrict__ metric)
{
    const int mod = blockIdx.y, bp = blockIdx.x * 256 + threadIdx.x;
    float s = 0.f, ss = 0.f, zc = 0.f;
#pragma unroll
    for (int c = 0; c < 8; c++) {
        const long long o = (((long long)mod * 8 + c) * 4096 + bp) * 3;
        s += part[o]; ss += part[o+1]; zc += part[o+2];
    }
    const float iv = 1.f / fmaxf(sqrtf(ss), 1e-12f);
    inv[mod * 4096 + bp] = iv;
    float met;
    if (mod == 0) { const float S = s*iv, SS = ss*iv*iv; met = (SS - S*S*(1.f/1024.f)) * (1.f/1023.f); }
    else met = zc * (1.f/1024.f);
    metric[mod * 4096 + bp] = met;
}

// transpose [c][p]->[p][c], scale, emit fp32 + bf16 hi/lo
__global__ void trans_norm_split(const float* __restrict__ feat, const float* __restrict__ inv,
    float* __restrict__ crossT, bf16* __restrict__ fhi, bf16* __restrict__ flo)
{
    __shared__ float t[32][33];
    const int mb = blockIdx.z;
    const float* src = feat + (long long)mb * 1048576;
    const int c0 = blockIdx.y * 32, p0 = blockIdx.x * 32;
    const int tx = threadIdx.x & 31, ty = threadIdx.x >> 5;
    for (int r = ty; r < 32; r += 8) t[r][tx] = src[(long long)(c0 + r) * 1024 + p0 + tx];
    __syncthreads();
    for (int r = ty; r < 32; r += 8) {
        const int p = p0 + r, c = c0 + tx;
        const float v = t[tx][r] * inv[(mb >> 2) * 4096 + (mb & 3) * 1024 + p];
        const long long d = (long long)mb * 1048576 + (long long)p * 1024 + c;
        crossT[d] = v;
        const bf16 h = __float2bfloat16(v);
        fhi[d] = h;
        flo[d] = __float2bfloat16(v - __bfloat162float(h));
    }
}

__global__ void split_w(const float* __restrict__ src, bf16* __restrict__ hi, bf16* __restrict__ lo)
{
    const long long i = (long long)blockIdx.x * 256 + threadIdx.x;
    const float x = src[i];
    const bf16 h = __float2bfloat16(x);
    hi[i] = h; lo[i] = __float2bfloat16(x - __bfloat162float(h));
}

// ---------------- fp32 attention core ([b][p][c]) ----------------
__global__ void __launch_bounds__(256) scores_v2(const float* __restrict__ Q, const float* __restrict__ K, float* __restrict__ Sp)
{
    const int z = blockIdx.z, b = z >> 3, n = z & 7, split = blockIdx.x;
    const float* Qb = Q + (long long)b * 1048576 + n * 128;
    const float* Kb = K + (long long)b * 1048576 + n * 128;
    __shared__ float Qs[16][128], Ks[16][128];
    const int tid = threadIdx.x, tx = tid & 15, ty = tid >> 4;
    float acc[8][8];
#pragma unroll
    for (int i = 0; i < 8; i++)
#pragma unroll
        for (int j = 0; j < 8; j++) acc[i][j] = 0.f;
    for (int t = 0; t < 8; t++) {
        const int pb = split * 128 + t * 16;
#pragma unroll
        for (int j = 0; j < 2; j++) {
            const int idx = tid + j * 256, pr = idx >> 5, c4 = (idx & 31) * 4;
            *(float4*)&Qs[pr][c4] = *(const float4*)&Qb[(long long)(pb + pr) * 1024 + c4];
            *(float4*)&Ks[pr][c4] = *(const float4*)&Kb[(long long)(pb + pr) * 1024 + c4];
        }
        __syncthreads();
#pragma unroll
        for (int kk = 0; kk < 16; kk++) {
            float a8[8], b8[8];
            *(float4*)a8 = *(float4*)&Qs[kk][ty*8]; *(float4*)(a8+4) = *(float4*)&Qs[kk][ty*8+4];
            *(float4*)b8 = *(float4*)&Ks[kk][tx*8]; *(float4*)(b8+4) = *(float4*)&Ks[kk][tx*8+4];
#pragma unroll
            for (int i = 0; i < 8; i++)
#pragma unroll
                for (int j = 0; j < 8; j++) acc[i][j] += a8[i] * b8[j];
        }
        __syncthreads();
    }
    const long long base = ((long long)split * 32 + z) * 16384;
#pragma unroll
    for (int i = 0; i < 8; i++)
#pragma unroll
        for (int j = 0; j < 8; j++)
            Sp[base + (long long)(ty*8+i) * 128 + tx*8 + j] = acc[i][j];
}

__global__ void softmax_v2(const float* __restrict__ Sp, float* __restrict__ attnT)
{
    const int z = blockIdx.y, h = blockIdx.x, t = threadIdx.x;
    float s = 0.f;
#pragma unroll
    for (int sp = 0; sp < 8; sp++) s += Sp[((long long)sp * 32 + z) * 16384 + h * 128 + t];
    s *= ATT_SCALE;
    __shared__ float red[128];
    red[t] = s; __syncthreads();
    for (int o = 64; o > 0; o >>= 1) { if (t < o) red[t] = fmaxf(red[t], red[t+o]); __syncthreads(); }
    const float mx = red[0]; __syncthreads();
    const float e = expf(s - mx);
    red[t] = e; __syncthreads();
    for (int o = 64; o > 0; o >>= 1) { if (t < o) red[t] += red[t+o]; __syncthreads(); }
    attnT[(long long)z * 16384 + t * 128 + h] = e / red[0];
}

__global__ void __launch_bounds__(256) av_v2(const float* __restrict__ V, const float* __restrict__ attnT,
    bf16* __restrict__ Oh, bf16* __restrict__ Ol)
{
    const int z = blockIdx.z, b = z >> 3, n = z & 7, p0 = blockIdx.x * 128;
    const float* Vb = V + (long long)b * 1048576 + n * 128;
    const float* At = attnT + (long long)z * 16384;
    __shared__ float As[8][128], Bs[8][128];
    const int tid = threadIdx.x, tx = tid & 15, ty = tid >> 4;
    float acc[8][8];
#pragma unroll
    for (int i = 0; i < 8; i++)
#pragma unroll
        for (int j = 0; j < 8; j++) acc[i][j] = 0.f;
    for (int k0 = 0; k0 < 128; k0 += 8) {
        const int row = tid >> 1, k4 = (tid & 1) * 4;
        float4 av = *(const float4*)&Vb[(long long)(p0 + row) * 1024 + k0 + k4];
        As[k4][row] = av.x; As[k4+1][row] = av.y; As[k4+2][row] = av.z; As[k4+3][row] = av.w;
        const int kr = tid >> 5, i4 = (tid & 31) * 4;
        *(float4*)&Bs[kr][i4] = *(const float4*)&At[(k0 + kr) * 128 + i4];
        __syncthreads();
#pragma unroll
        for (int kk = 0; kk < 8; kk++) {
            float a8[8], b8[8];
            *(float4*)a8 = *(float4*)&As[kk][ty*8]; *(float4*)(a8+4) = *(float4*)&As[kk][ty*8+4];
            *(float4*)b8 = *(float4*)&Bs[kk][tx*8]; *(float4*)(b8+4) = *(float4*)&Bs[kk][tx*8+4];
#pragma unroll
            for (int i = 0; i < 8; i++)
#pragma unroll
                for (int j = 0; j < 8; j++) acc[i][j] += a8[i] * b8[j];
        }
        __syncthreads();
    }
    const long long ob = (long long)b * 1048576 + n * 128;
#pragma unroll
    for (int i = 0; i < 8; i++)
#pragma unroll
        for (int j = 0; j < 8; j++) {
            const float x = acc[i][j];
            const bf16 h = __float2bfloat16(x);
            const long long d = ob + (long long)(p0 + ty*8 + i) * 1024 + tx*8 + j;
            Oh[d] = h; Ol[d] = __float2bfloat16(x - __bfloat162float(h));
        }
}

// ---------------- SE / gates / fuse ([p][c]) ----------------
__global__ void se_pool_v2(const float* __restrict__ crossT, float* __restrict__ pool)
{
    const int mb = blockIdx.y, c = blockIdx.x * 128 + threadIdx.x;
    const float* base = crossT + (long long)mb * 1048576 + c;
    float s = 0.f;
#pragma unroll 4
    for (int p = 0; p < 1024; p++) s += base[(long long)p * 1024];
    pool[mb * 1024 + c] = s * (1.f / 1024.f);
}
__global__ void se_mlp(const float* __restrict__ pool,
    const float* __restrict__ w1, const float* __restrict__ b1,
    const float* __restrict__ w2, const float* __restrict__ b2, float* __restrict__ se)
{
    const int mb = blockIdx.x, mod = mb >> 2, tid = threadIdx.x;
    __shared__ float ps[1024], hh[64];
    for (int i = tid; i < 1024; i += 256) ps[i] = pool[mb * 1024 + i];
    __syncthreads();
    if (tid < 64) {
        float a = b1[mod * 64 + tid];
        const float* w = w1 + ((long long)mod * 64 + tid) * 1024;
        for (int c = 0; c < 1024; c++) a += w[c] * ps[c];
        hh[tid] = fmaxf(a, 0.f);
    }
    __syncthreads();
#pragma unroll
    for (int q = 0; q < 4; q++) {
        const int c = tid + q * 256;
        float a = b2[mod * 1024 + c];
        const float* w = w2 + ((long long)mod * 1024 + c) * 64;
#pragma unroll
        for (int j = 0; j < 64; j++) a += w[j] * hh[j];
        se[mb * 1024 + c] = 1.f / (1.f + expf(-a));
    }
}

// gates with SE applied inline (crossT stays pre-SE; refs = crossT * se)
__global__ void __launch_bounds__(128) gate_v2(const float* __restrict__ crossT,
    const float* __restrict__ se,
    const float* __restrict__ metric, const float* __restrict__ gw, const float* __restrict__ gb,
    float* __restrict__ gates)
{
    const int bp = blockIdx.x, b = bp >> 10, p = bp & 1023, t = threadIdx.x;
    float a0 = 0.f, a1 = 0.f, a2 = 0.f;
    for (int mod = 0; mod < 3; mod++) {
        const int mb = mod * 4 + b;
        const float* base = crossT + ((long long)mb * 1024 + p) * 1024;
        const float* seb = se + (long long)mb * 1024;
        for (int c = t; c < 1024; c += 128) {
            const float v = base[c] * seb[c];
            a0 += gw[0*3075 + mod*1024 + c] * v;
            a1 += gw[1*3075 + mod*1024 + c] * v;
            a2 += gw[2*3075 + mod*1024 + c] * v;
        }
    }
    for (int o = 16; o > 0; o >>= 1) {
        a0 += __shfl_xor_sync(0xFFFFFFFF, a0, o);
        a1 += __shfl_xor_sync(0xFFFFFFFF, a1, o);
        a2 += __shfl_xor_sync(0xFFFFFFFF, a2, o);
    }
    __shared__ float r[4][3];
    if ((t & 31) == 0) { r[t>>5][0] = a0; r[t>>5][1] = a1; r[t>>5][2] = a2; }
    __syncthreads();
    if (t == 0) {
        float s0 = gb[0], s1 = gb[1], s2 = gb[2];
        for (int i = 0; i < 4; i++) { s0 += r[i][0]; s1 += r[i][1]; s2 += r[i][2]; }
        for (int mod = 0; mod < 3; mod++) {
            const float m = metric[mod * 4096 + bp];
            s0 += gw[0*3075 + 3072 + mod] * m;
            s1 += gw[1*3075 + 3072 + mod] * m;
            s2 += gw[2*3075 + 3072 + mod] * m;
        }
        gates[0*4096 + bp] = 1.f/(1.f+expf(-s0));
        gates[1*4096 + bp] = 1.f/(1.f+expf(-s1));
        gates[2*4096 + bp] = 1.f/(1.f+expf(-s2));
    }
}

__global__ void fuse_conv(const float* __restrict__ crossT, const float* __restrict__ se,
    const float* __restrict__ gates, bf16* __restrict__ fhi, bf16* __restrict__ flo)
{
    const long long idx = (long long)blockIdx.x * 256 + threadIdx.x;
    const int c = (int)(idx & 1023);
    const long long rr = idx >> 10;
    const int p = (int)(rr & 1023), mb = (int)(rr >> 10), mod = mb >> 2, b = mb & 3;
    const float x = crossT[idx] * se[(long long)mb * 1024 + c] * gates[mod * 4096 + b * 1024 + p];
    const long long d = ((long long)b * 1024 + p) * 3072 + mod * 1024 + c;
    const bf16 h = __float2bfloat16(x);
    fhi[d] = h; flo[d] = __float2bfloat16(x - __bfloat162float(h));
}

// ---------------- host ----------------
extern "C" void kernel_launch(void* const* d_in, const int* in_sizes, int n_in,
                              void* d_out, int out_size)
{
    const float *rgb=(const float*)d_in[0], *depth=(const float*)d_in[1], *lidar=(const float*)d_in[2];
    const float *prw=(const float*)d_in[3], *prb=(const float*)d_in[4], *pdw=(const float*)d_in[5], *pdb=(const float*)d_in[6];
    const float *plw=(const float*)d_in[7], *plb=(const float*)d_in[8];
    const float *aqw=(const float*)d_in[9], *aqb=(const float*)d_in[10], *akw=(const float*)d_in[11], *akb=(const float*)d_in[12];
    const float *avw=(const float*)d_in[13], *avb=(const float*)d_in[14], *aow=(const float*)d_in[15], *aob=(const float*)d_in[16];
    const float *sew1=(const float*)d_in[17], *seb1=(const float*)d_in[18], *sew2=(const float*)d_in[19], *seb2=(const float*)d_in[20];
    const float *gw=(const float*)d_in[21], *gb=(const float*)d_in[22], *fw=(const float*)d_in[23], *fb=(const float*)d_in[24];
    float* out = (float*)d_out;

    char* A = nullptr;
    cudaGetSymbolAddress((void**)&A, g_arena);
    size_t o = 0;
    auto al = [&](size_t bytes) { char* p = A + o; o += (bytes + 1023) & ~(size_t)1023; return p; };
    float* feat   = (float*)al(50331648);
    float* crossT = (float*)al(50331648);
    float* q      = (float*)al(16777216);
    float* k      = (float*)al(16777216);
    float* v      = (float*)al(16777216);
    float* spart  = (float*)al(16777216);
    float* attnT  = (float*)al(2097152);
    float* part   = (float*)al(1179648);
    float* inv    = (float*)al(49152);
    float* metric = (float*)al(49152);
    float* pool   = (float*)al(49152);
    float* se     = (float*)al(49152);
    float* gates  = (float*)al(49152);
    bf16* f_hi  = (bf16*)al(25165824);
    bf16* f_lo  = (bf16*)al(25165824);
    bf16* at_hi = (bf16*)al(8388608);
    bf16* at_lo = (bf16*)al(8388608);
    bf16* fu_hi = (bf16*)al(25165824);
    bf16* fu_lo = (bf16*)al(25165824);
    bf16* wq_hi = (bf16*)al(12582912); bf16* wq_lo = (bf16*)al(12582912);
    bf16* wk_hi = (bf16*)al(12582912); bf16* wk_lo = (bf16*)al(12582912);
    bf16* wv_hi = (bf16*)al(12582912); bf16* wv_lo = (bf16*)al(12582912);
    bf16* wo_hi = (bf16*)al(12582912); bf16* wo_lo = (bf16*)al(12582912);
    bf16* wf_hi = (bf16*)al(18874368); bf16* wf_lo = (bf16*)al(18874368);

    cudaFuncSetAttribute(hmma_gemm, cudaFuncAttributeMaxDynamicSharedMemorySize, HG_SMEM);

    split_w<<<24576, 256>>>(aqw, wq_hi, wq_lo);
    split_w<<<24576, 256>>>(akw, wk_hi, wk_lo);
    split_w<<<24576, 256>>>(avw, wv_hi, wv_lo);
    split_w<<<24576, 256>>>(aow, wo_hi, wo_lo);
    split_w<<<36864, 256>>>(fw,  wf_hi, wf_lo);

    gemm128<<<dim3(8,8,4), 256>>>(prw, rgb,   prb, feat,            512, 524288);
    gemm128<<<dim3(8,8,4), 256>>>(pdw, depth, pdb, feat + 4194304,  256, 262144);
    gemm128<<<dim3(8,8,4), 256>>>(plw, lidar, plb, feat + 8388608,   64, 65536);

    colreduce<<<dim3(16,8,3), 256>>>(feat, part);
    finalize_stats<<<dim3(16,3), 256>>>(part, inv, metric);
    trans_norm_split<<<dim3(32,32,12), 256>>>(feat, inv, crossT, f_hi, f_lo);

    const int qmod[6] = {0,0,1,1,2,2}, kmod[6] = {1,2,0,2,0,1};
    for (int i = 0; i < 6; i++) {
        const long long qo = (long long)qmod[i] * 4194304, ko = (long long)kmod[i] * 4194304;
        const long long wOff = (long long)i * 1048576;
        hmma_gemm<<<dim3(8,8,4), 256, HG_SMEM>>>(f_hi+qo, f_lo+qo, 1048576, 1024,
            wq_hi+wOff, wq_lo+wOff, aqb+i*1024, q, 1048576, 1024, 1024, 0);
        hmma_gemm<<<dim3(8,8,4), 256, HG_SMEM>>>(f_hi+ko, f_lo+ko, 1048576, 1024,
            wk_hi+wOff, wk_lo+wOff, akb+i*1024, k, 1048576, 1024, 1024, 0);
        hmma_gemm<<<dim3(8,8,4), 256, HG_SMEM>>>(f_hi+ko, f_lo+ko, 1048576, 1024,
            wv_hi+wOff, wv_lo+wOff, avb+i*1024, v, 1048576, 1024, 1024, 0);
        scores_v2<<<dim3(8,1,32), 256>>>(q, k, spart);
        softmax_v2<<<dim3(128,32), 128>>>(spart, attnT);
        av_v2<<<dim3(8,1,32), 256>>>(v, attnT, at_hi, at_lo);
        hmma_gemm<<<dim3(8,8,4), 256, HG_SMEM>>>(at_hi, at_lo, 1048576, 1024,
            wo_hi+wOff, wo_lo+wOff, aob+i*1024, crossT + qmod[i]*4194304, 1048576, 1024, 1024, 1);
    }

    se_pool_v2<<<dim3(8,12), 128>>>(crossT, pool);
    se_mlp<<<12, 256>>>(pool, sew1, seb1, sew2, seb2, se);
    gate_v2<<<4096, 128>>>(crossT, se, metric, gw, gb, gates);
    fuse_conv<<<49152, 256>>>(crossT, se, gates, fu_hi, fu_lo);
    hmma_gemm<<<dim3(24,8,4), 256, HG_SMEM>>>(fu_hi, fu_lo, 3145728, 3072,
        wf_hi, wf_lo, fb, out, 3145728, 1024, 3072, 2);
}

// round 10
// speedup vs baseline: 3.9507x; 1.8930x over previous
#include <cuda_runtime.h>
#include <cuda_fp16.h>
#include <cstdint>
#include <math.h>

static const float ATT_SCALE = 0.08838834764831845f;

__device__ __align__(1024) char g_arena[700ull << 20];

// ---------------- warp-MMA helper (fp16) ----------------
__device__ __forceinline__ void mma16816(float* d, const uint32_t* a, const uint32_t* b) {
    asm volatile("mma.sync.aligned.m16n8k16.row.col.f32.f16.f16.f32 "
        "{%0,%1,%2,%3}, {%4,%5,%6,%7}, {%8,%9}, {%0,%1,%2,%3};"
        : "+f"(d[0]), "+f"(d[1]), "+f"(d[2]), "+f"(d[3])
        : "r"(a[0]), "r"(a[1]), "r"(a[2]), "r"(a[3]), "r"(b[0]), "r"(b[1]));
}
__device__ __forceinline__ uint32_t smem_u32(const void* p) {
    uint32_t a; asm("{ .reg .u64 t; cvta.to.shared.u64 t, %1; cvt.u32.u64 %0, t; }" : "=r"(a) : "l"(p)); return a;
}
#define CPA(dst, src) asm volatile("cp.async.cg.shared.global [%0], [%1], 16;" :: "r"(dst), "l"(src))
#define CP_COMMIT()   asm volatile("cp.async.commit_group;")
#define CP_WAIT1()    asm volatile("cp.async.wait_group 1;")
#define CP_WAIT0()    asm volatile("cp.async.wait_group 0;")

// ---------------- fp16 HMMA GEMM, cp.async double-buffered ----------------
// D[p,n] (+)= sum_k A[p,k]*B[n,k] + bias[n]; A batched, B shared.
// mode: 0 store, 1 accumulate into C, 2 transposed store C[n*ldc+p]
#define SSTR 40
#define ARR  5120
#define STG  10240
#define HG_SMEM 40960
__global__ void __launch_bounds__(256) hmma_gemm(
    const half* __restrict__ Ap, long long aBatch, int lda,
    const half* __restrict__ Bp,
    const float* __restrict__ bias, float* __restrict__ C,
    long long cBatch, int ldc, int K, int mode)
{
    extern __shared__ half sm[];
    const uint32_t smb = smem_u32(sm);
    const int tid = threadIdx.x, lane = tid & 31, warp = tid >> 5;
    const int wm = warp >> 2, wn = warp & 3;
    const int gid = lane >> 2, tig = lane & 3;
    const int z = blockIdx.z;
    const int n0 = blockIdx.x * 128, p0 = blockIdx.y * 128;
    const uint4* Ag = (const uint4*)(Ap + (long long)z * aBatch);
    const uint4* Bg = (const uint4*)Bp;
    const int lda8 = lda >> 3, K8 = K >> 3;
    const int NC = K >> 5;

    const int r0 = tid >> 2, c0 = tid & 3;
    const uint32_t dOff0 = (uint32_t)((r0 * SSTR + c0 * 8) * 2);
    const uint32_t dOff1 = (uint32_t)(((r0 + 64) * SSTR + c0 * 8) * 2);

    float acc[64];
#pragma unroll
    for (int i = 0; i < 64; i++) acc[i] = 0.f;

#define ISSUE(cc, ss) do { \
        const int kb = (cc) << 2; \
        const uint32_t sb_ = smb + (ss) * (STG * 2); \
        CPA(sb_ + dOff0,          Ag + (long long)(p0 + r0) * lda8 + kb + c0); \
        CPA(sb_ + dOff1,          Ag + (long long)(p0 + r0 + 64) * lda8 + kb + c0); \
        CPA(sb_ + ARR*2 + dOff0,  Bg + (long long)(n0 + r0) * K8 + kb + c0); \
        CPA(sb_ + ARR*2 + dOff1,  Bg + (long long)(n0 + r0 + 64) * K8 + kb + c0); \
        CP_COMMIT(); \
    } while (0)

    ISSUE(0, 0);
    for (int c = 0; c < NC; c++) {
        if (c + 1 < NC) { ISSUE(c + 1, (c + 1) & 1); CP_WAIT1(); }
        else            { CP_WAIT0(); }
        __syncthreads();
        const half* sA = sm + (c & 1) * STG;
        const half* sB = sA + ARR;
#pragma unroll
        for (int ks = 0; ks < 2; ks++) {
            const int k0 = ks * 16 + tig * 2;
            uint32_t bf[4][2];
#pragma unroll
            for (int nt = 0; nt < 4; nt++) {
                const int n = wn * 32 + nt * 8 + gid;
                bf[nt][0] = *(const uint32_t*)&sB[n * SSTR + k0];
                bf[nt][1] = *(const uint32_t*)&sB[n * SSTR + k0 + 8];
            }
#pragma unroll
            for (int mt = 0; mt < 4; mt++) {
                const int r = wm * 64 + mt * 16 + gid;
                uint32_t af[4];
                af[0] = *(const uint32_t*)&sA[r * SSTR + k0];
                af[1] = *(const uint32_t*)&sA[(r + 8) * SSTR + k0];
                af[2] = *(const uint32_t*)&sA[r * SSTR + k0 + 8];
                af[3] = *(const uint32_t*)&sA[(r + 8) * SSTR + k0 + 8];
#pragma unroll
                for (int nt = 0; nt < 4; nt++)
                    mma16816(&acc[(mt * 4 + nt) * 4], af, bf[nt]);
            }
        }
        __syncthreads();
    }
#undef ISSUE

#pragma unroll
    for (int mt = 0; mt < 4; mt++) {
#pragma unroll
        for (int nt = 0; nt < 4; nt++) {
            const float* d = &acc[(mt * 4 + nt) * 4];
            const int r = p0 + wm * 64 + mt * 16 + gid;
            const int n = n0 + wn * 32 + nt * 8 + tig * 2;
            const float b0 = bias ? bias[n] : 0.f;
            const float b1 = bias ? bias[n + 1] : 0.f;
            if (mode == 2) {
                float* Cb = C + (long long)z * cBatch;
                Cb[(long long)n * ldc + r]           = d[0] + b0;
                Cb[(long long)(n + 1) * ldc + r]     = d[1] + b1;
                Cb[(long long)n * ldc + r + 8]       = d[2] + b0;
                Cb[(long long)(n + 1) * ldc + r + 8] = d[3] + b1;
            } else {
                float* c0p = C + (long long)z * cBatch + (long long)r * ldc + n;
                float* c1p = C + (long long)z * cBatch + (long long)(r + 8) * ldc + n;
                float2 v0 = make_float2(d[0] + b0, d[1] + b1);
                float2 v1 = make_float2(d[2] + b0, d[3] + b1);
                if (mode == 1) {
                    float2 o0 = *(float2*)c0p, o1 = *(float2*)c1p;
                    v0.x += o0.x; v0.y += o0.y; v1.x += o1.x; v1.y += o1.y;
                }
                *(float2*)c0p = v0;
                *(float2*)c1p = v1;
            }
        }
    }
}

// ---------------- weight prep ----------------
// combined QKV weights: [3][6144][1024] fp16
__global__ void split_attn_w(const float* __restrict__ aqw, const float* __restrict__ akw,
                             const float* __restrict__ avw, half* __restrict__ dst)
{
    const long long idx = (long long)blockIdx.x * 256 + threadIdx.x;  // 3*6144*1024
    const int k = (int)(idx & 1023);
    const int row = (int)((idx >> 10) % 6144);
    const int m = (int)(idx / 6291456);
    const int grp = row >> 10, r = row & 1023;
    const int kb0[3] = {2, 0, 1}, kb1[3] = {4, 5, 3};
    const float* src; int blk;
    if (grp == 0)      { src = aqw; blk = 2 * m; }
    else if (grp == 1) { src = aqw; blk = 2 * m + 1; }
    else if (grp == 2) { src = akw; blk = kb0[m]; }
    else if (grp == 3) { src = akw; blk = kb1[m]; }
    else if (grp == 4) { src = avw; blk = kb0[m]; }
    else               { src = avw; blk = kb1[m]; }
    dst[idx] = __float2half(src[(long long)blk * 1048576 + r * 1024 + k]);
}
// combined O weights K-concat: [3][1024][2048] fp16
__global__ void split_o_w(const float* __restrict__ aow, half* __restrict__ dst)
{
    const long long idx = (long long)blockIdx.x * 256 + threadIdx.x;  // 3*1024*2048
    const int k2 = (int)(idx & 2047);
    const int n = (int)((idx >> 11) & 1023);
    const int m = (int)(idx >> 21);
    const int blk = 2 * m + (k2 >> 10), k = k2 & 1023;
    dst[idx] = __float2half(aow[(long long)blk * 1048576 + n * 1024 + k]);
}
__global__ void cvt_w(const float* __restrict__ src, half* __restrict__ dst)
{
    const long long i = (long long)blockIdx.x * 256 + threadIdx.x;
    dst[i] = __float2half(src[i]);
}
__global__ void bias_qkv(const float* __restrict__ aqb, const float* __restrict__ akb,
                         const float* __restrict__ avb, float* __restrict__ dst)
{
    const int idx = blockIdx.x * 256 + threadIdx.x;  // 3*6144
    const int row = idx % 6144, m = idx / 6144;
    const int grp = row >> 10, r = row & 1023;
    const int kb0[3] = {2, 0, 1}, kb1[3] = {4, 5, 3};
    const float* src; int blk;
    if (grp == 0)      { src = aqb; blk = 2 * m; }
    else if (grp == 1) { src = aqb; blk = 2 * m + 1; }
    else if (grp == 2) { src = akb; blk = kb0[m]; }
    else if (grp == 3) { src = akb; blk = kb1[m]; }
    else if (grp == 4) { src = avb; blk = kb0[m]; }
    else               { src = avb; blk = kb1[m]; }
    dst[idx] = src[blk * 1024 + r];
}
__global__ void bias_o(const float* __restrict__ aob, float* __restrict__ dst)
{
    const int idx = blockIdx.x * 256 + threadIdx.x;  // 3*1024
    const int m = idx >> 10, n = idx & 1023;
    dst[idx] = aob[2 * m * 1024 + n] + aob[(2 * m + 1) * 1024 + n];
}

// ---------------- fp32 projection GEMM ----------------
__global__ void __launch_bounds__(256) gemm128(
    const float* __restrict__ A, const float* __restrict__ X, const float* __restrict__ bias,
    float* __restrict__ Y, int K, long long xStride)
{
    const float* Xb = X + (long long)blockIdx.z * xStride;
    float* Yb = Y + (long long)blockIdx.z * 1048576;
    const int m0 = blockIdx.y * 128, p0 = blockIdx.x * 128;
    __shared__ float As[8][128], Bs[8][128];
    const int tid = threadIdx.x, tx = tid & 15, ty = tid >> 4;
    float acc[8][8];
#pragma unroll
    for (int i = 0; i < 8; i++)
#pragma unroll
        for (int j = 0; j < 8; j++) acc[i][j] = 0.f;
    for (int k0 = 0; k0 < K; k0 += 8) {
        const int ar = tid >> 1, ak = (tid & 1) * 4;
        float4 av = *(const float4*)&A[(long long)(m0 + ar) * K + k0 + ak];
        As[ak][ar] = av.x; As[ak+1][ar] = av.y; As[ak+2][ar] = av.z; As[ak+3][ar] = av.w;
        const int bk = tid >> 5, bp = (tid & 31) * 4;
        *(float4*)&Bs[bk][bp] = *(const float4*)&Xb[(long long)(k0 + bk) * 1024 + p0 + bp];
        __syncthreads();
#pragma unroll
        for (int kk = 0; kk < 8; kk++) {
            float ar8[8], br8[8];
            *(float4*)ar8 = *(float4*)&As[kk][ty*8]; *(float4*)(ar8+4) = *(float4*)&As[kk][ty*8+4];
            *(float4*)br8 = *(float4*)&Bs[kk][tx*8]; *(float4*)(br8+4) = *(float4*)&Bs[kk][tx*8+4];
#pragma unroll
            for (int i = 0; i < 8; i++)
#pragma unroll
                for (int j = 0; j < 8; j++) acc[i][j] += ar8[i] * br8[j];
        }
        __syncthreads();
    }
#pragma unroll
    for (int i = 0; i < 8; i++) {
        const float bv = bias[m0 + ty*8 + i];
#pragma unroll
        for (int j = 0; j < 8; j++)
            Yb[(long long)(m0 + ty*8 + i) * 1024 + p0 + tx*8 + j] = acc[i][j] + bv;
    }
}

// ---------------- stats ----------------
__global__ void colreduce(const float* __restrict__ feat, float* __restrict__ part)
{
    const int mod = blockIdx.z, cch = blockIdx.y;
    const int bp = blockIdx.x * 256 + threadIdx.x;
    const float* base = feat + (((long long)(mod * 4 + (bp >> 10)) * 1024 + cch * 128) * 1024) + (bp & 1023);
    float s = 0.f, ss = 0.f, zc = 0.f;
    for (int c = 0; c < 128; c++) {
        float v = base[(long long)c * 1024];
        s += v; ss += v * v; zc += (v == 0.f) ? 1.f : 0.f;
    }
    const long long o = (((long long)mod * 8 + cch) * 4096 + bp) * 3;
    part[o] = s; part[o+1] = ss; part[o+2] = zc;
}
__global__ void finalize_stats(const float* __restrict__ part, float* __restrict__ inv, float* __restrict__ metric)
{
    const int mod = blockIdx.y, bp = blockIdx.x * 256 + threadIdx.x;
    float s = 0.f, ss = 0.f, zc = 0.f;
#pragma unroll
    for (int c = 0; c < 8; c++) {
        const long long o = (((long long)mod * 8 + c) * 4096 + bp) * 3;
        s += part[o]; ss += part[o+1]; zc += part[o+2];
    }
    const float iv = 1.f / fmaxf(sqrtf(ss), 1e-12f);
    inv[mod * 4096 + bp] = iv;
    float met;
    if (mod == 0) { const float S = s*iv, SS = ss*iv*iv; met = (SS - S*S*(1.f/1024.f)) * (1.f/1023.f); }
    else met = zc * (1.f/1024.f);
    metric[mod * 4096 + bp] = met;
}

// transpose [c][p]->[p][c], scale, emit fp32 + fp16
__global__ void trans_norm_split(const float* __restrict__ feat, const float* __restrict__ inv,
    float* __restrict__ crossT, half* __restrict__ fh)
{
    __shared__ float t[32][33];
    const int mb = blockIdx.z;
    const float* src = feat + (long long)mb * 1048576;
    const int c0 = blockIdx.y * 32, p0 = blockIdx.x * 32;
    const int tx = threadIdx.x & 31, ty = threadIdx.x >> 5;
    for (int r = ty; r < 32; r += 8) t[r][tx] = src[(long long)(c0 + r) * 1024 + p0 + tx];
    __syncthreads();
    for (int r = ty; r < 32; r += 8) {
        const int p = p0 + r, c = c0 + tx;
        const float v = t[tx][r] * inv[(mb >> 2) * 4096 + (mb & 3) * 1024 + p];
        const long long d = (long long)mb * 1048576 + (long long)p * 1024 + c;
        crossT[d] = v;
        fh[d] = __float2half(v);
    }
}

// ---------------- batched fp32 attention core ----------------
__constant__ int c_kmod[6] = {1, 2, 0, 2, 0, 1};

__global__ void __launch_bounds__(256) scores_v3(const float* __restrict__ Y, float* __restrict__ Sp)
{
    const int z = blockIdx.z, b = z >> 3, n = z & 7;
    const int blk = blockIdx.y, split = blockIdx.x;
    const int qm = blk >> 1, km = c_kmod[blk];
    const int qoff = (blk & 1) << 10;
    const int koff = 2048 + ((blk > 2) ? 1024 : 0);
    const float* Qb = Y + (long long)qm * 25165824 + (long long)b * 6291456 + qoff + n * 128;
    const float* Kb = Y + (long long)km * 25165824 + (long long)b * 6291456 + koff + n * 128;
    __shared__ float Qs[16][128], Ks[16][128];
    const int tid = threadIdx.x, tx = tid & 15, ty = tid >> 4;
    float acc[8][8];
#pragma unroll
    for (int i = 0; i < 8; i++)
#pragma unroll
        for (int j = 0; j < 8; j++) acc[i][j] = 0.f;
    for (int t = 0; t < 16; t++) {
        const int pb = split * 256 + t * 16;
#pragma unroll
        for (int j = 0; j < 2; j++) {
            const int idx = tid + j * 256, pr = idx >> 5, c4 = (idx & 31) * 4;
            *(float4*)&Qs[pr][c4] = *(const float4*)&Qb[(long long)(pb + pr) * 6144 + c4];
            *(float4*)&Ks[pr][c4] = *(const float4*)&Kb[(long long)(pb + pr) * 6144 + c4];
        }
        __syncthreads();
#pragma unroll
        for (int kk = 0; kk < 16; kk++) {
            float a8[8], b8[8];
            *(float4*)a8 = *(float4*)&Qs[kk][ty*8]; *(float4*)(a8+4) = *(float4*)&Qs[kk][ty*8+4];
            *(float4*)b8 = *(float4*)&Ks[kk][tx*8]; *(float4*)(b8+4) = *(float4*)&Ks[kk][tx*8+4];
#pragma unroll
            for (int i = 0; i < 8; i++)
#pragma unroll
                for (int j = 0; j < 8; j++) acc[i][j] += a8[i] * b8[j];
        }
        __syncthreads();
    }
    const long long base = (((long long)split * 6 + blk) * 32 + z) * 16384;
#pragma unroll
    for (int i = 0; i < 8; i++)
#pragma unroll
        for (int j = 0; j < 8; j++)
            Sp[base + (long long)(ty*8+i) * 128 + tx*8 + j] = acc[i][j];
}

__global__ void softmax_v3(const float* __restrict__ Sp, float* __restrict__ attnT)
{
    const int bz = blockIdx.y;      // blk*32+z
    const int h = blockIdx.x, t = threadIdx.x;
    float s = 0.f;
#pragma unroll
    for (int sp = 0; sp < 4; sp++) s += Sp[(((long long)sp * 192) + bz) * 16384 + h * 128 + t];
    s *= ATT_SCALE;
    __shared__ float red[128];
    red[t] = s; __syncthreads();
    for (int o = 64; o > 0; o >>= 1) { if (t < o) red[t] = fmaxf(red[t], red[t+o]); __syncthreads(); }
    const float mx = red[0]; __syncthreads();
    const float e = expf(s - mx);
    red[t] = e; __syncthreads();
    for (int o = 64; o > 0; o >>= 1) { if (t < o) red[t] += red[t+o]; __syncthreads(); }
    attnT[(long long)bz * 16384 + t * 128 + h] = e / red[0];
}

__global__ void __launch_bounds__(256) av_v3(const float* __restrict__ Y, const float* __restrict__ attnT,
    half* __restrict__ atc)
{
    const int z = blockIdx.z, b = z >> 3, n = z & 7;
    const int blk = blockIdx.y, p0 = blockIdx.x * 128;
    const int qm = blk >> 1, km = c_kmod[blk];
    const int voff = 4096 + ((blk > 2) ? 1024 : 0);
    const float* Vb = Y + (long long)km * 25165824 + (long long)b * 6291456 + voff + n * 128;
    const float* At = attnT + ((long long)blk * 32 + z) * 16384;
    __shared__ float As[8][128], Bs[8][128];
    const int tid = threadIdx.x, tx = tid & 15, ty = tid >> 4;
    float acc[8][8];
#pragma unroll
    for (int i = 0; i < 8; i++)
#pragma unroll
        for (int j = 0; j < 8; j++) acc[i][j] = 0.f;
    for (int k0 = 0; k0 < 128; k0 += 8) {
        const int row = tid >> 1, k4 = (tid & 1) * 4;
        float4 av = *(const float4*)&Vb[(long long)(p0 + row) * 6144 + k0 + k4];
        As[k4][row] = av.x; As[k4+1][row] = av.y; As[k4+2][row] = av.z; As[k4+3][row] = av.w;
        const int kr = tid >> 5, i4 = (tid & 31) * 4;
        *(float4*)&Bs[kr][i4] = *(const float4*)&At[(k0 + kr) * 128 + i4];
        __syncthreads();
#pragma unroll
        for (int kk = 0; kk < 8; kk++) {
            float a8[8], b8[8];
            *(float4*)a8 = *(float4*)&As[kk][ty*8]; *(float4*)(a8+4) = *(float4*)&As[kk][ty*8+4];
            *(float4*)b8 = *(float4*)&Bs[kk][tx*8]; *(float4*)(b8+4) = *(float4*)&Bs[kk][tx*8+4];
#pragma unroll
            for (int i = 0; i < 8; i++)
#pragma unroll
                for (int j = 0; j < 8; j++) acc[i][j] += a8[i] * b8[j];
        }
        __syncthreads();
    }
    const long long ob = (long long)qm * 8388608 + (long long)b * 2097152;
    const int cb = ((blk & 1) << 10) + n * 128;
#pragma unroll
    for (int i = 0; i < 8; i++)
#pragma unroll
        for (int j = 0; j < 8; j++)
            atc[ob + (long long)(p0 + ty*8 + i) * 2048 + cb + tx*8 + j] = __float2half(acc[i][j]);
}

// ---------------- SE / gates / fuse ----------------
__global__ void se_pool_v2(const float* __restrict__ crossT, float* __restrict__ pool)
{
    const int mb = blockIdx.y, c = blockIdx.x * 128 + threadIdx.x;
    const float* base = crossT + (long long)mb * 1048576 + c;
    float s = 0.f;
#pragma unroll 4
    for (int p = 0; p < 1024; p++) s += base[(long long)p * 1024];
    pool[mb * 1024 + c] = s * (1.f / 1024.f);
}
__global__ void se_mlp(const float* __restrict__ pool,
    const float* __restrict__ w1, const float* __restrict__ b1,
    const float* __restrict__ w2, const float* __restrict__ b2, float* __restrict__ se)
{
    const int mb = blockIdx.x, mod = mb >> 2, tid = threadIdx.x;
    __shared__ float ps[1024], hh[64];
    for (int i = tid; i < 1024; i += 256) ps[i] = pool[mb * 1024 + i];
    __syncthreads();
    if (tid < 64) {
        float a = b1[mod * 64 + tid];
        const float* w = w1 + ((long long)mod * 64 + tid) * 1024;
        for (int c = 0; c < 1024; c++) a += w[c] * ps[c];
        hh[tid] = fmaxf(a, 0.f);
    }
    __syncthreads();
#pragma unroll
    for (int q = 0; q < 4; q++) {
        const int c = tid + q * 256;
        float a = b2[mod * 1024 + c];
        const float* w = w2 + ((long long)mod * 1024 + c) * 64;
#pragma unroll
        for (int j = 0; j < 64; j++) a += w[j] * hh[j];
        se[mb * 1024 + c] = 1.f / (1.f + expf(-a));
    }
}

__global__ void __launch_bounds__(128) gate_v2(const float* __restrict__ crossT,
    const float* __restrict__ se,
    const float* __restrict__ metric, const float* __restrict__ gw, const float* __restrict__ gb,
    float* __restrict__ gates)
{
    const int bp = blockIdx.x, b = bp >> 10, p = bp & 1023, t = threadIdx.x;
    float a0 = 0.f, a1 = 0.f, a2 = 0.f;
    for (int mod = 0; mod < 3; mod++) {
        const int mb = mod * 4 + b;
        const float* base = crossT + ((long long)mb * 1024 + p) * 1024;
        const float* seb = se + (long long)mb * 1024;
        for (int c = t; c < 1024; c += 128) {
            const float v = base[c] * seb[c];
            a0 += gw[0*3075 + mod*1024 + c] * v;
            a1 += gw[1*3075 + mod*1024 + c] * v;
            a2 += gw[2*3075 + mod*1024 + c] * v;
        }
    }
    for (int o = 16; o > 0; o >>= 1) {
        a0 += __shfl_xor_sync(0xFFFFFFFF, a0, o);
        a1 += __shfl_xor_sync(0xFFFFFFFF, a1, o);
        a2 += __shfl_xor_sync(0xFFFFFFFF, a2, o);
    }
    __shared__ float r[4][3];
    if ((t & 31) == 0) { r[t>>5][0] = a0; r[t>>5][1] = a1; r[t>>5][2] = a2; }
    __syncthreads();
    if (t == 0) {
        float s0 = gb[0], s1 = gb[1], s2 = gb[2];
        for (int i = 0; i < 4; i++) { s0 += r[i][0]; s1 += r[i][1]; s2 += r[i][2]; }
        for (int mod = 0; mod < 3; mod++) {
            const float m = metric[mod * 4096 + bp];
            s0 += gw[0*3075 + 3072 + mod] * m;
            s1 += gw[1*3075 + 3072 + mod] * m;
            s2 += gw[2*3075 + 3072 + mod] * m;
        }
        gates[0*4096 + bp] = 1.f/(1.f+expf(-s0));
        gates[1*4096 + bp] = 1.f/(1.f+expf(-s1));
        gates[2*4096 + bp] = 1.f/(1.f+expf(-s2));
    }
}

__global__ void fuse_conv(const float* __restrict__ crossT, const float* __restrict__ se,
    const float* __restrict__ gates, half* __restrict__ fh)
{
    const long long idx = (long long)blockIdx.x * 256 + threadIdx.x;
    const int c = (int)(idx & 1023);
    const long long rr = idx >> 10;
    const int p = (int)(rr & 1023), mb = (int)(rr >> 10), mod = mb >> 2, b = mb & 3;
    const float x = crossT[idx] * se[(long long)mb * 1024 + c] * gates[mod * 4096 + b * 1024 + p];
    fh[((long long)b * 1024 + p) * 3072 + mod * 1024 + c] = __float2half(x);
}

// ---------------- host ----------------
extern "C" void kernel_launch(void* const* d_in, const int* in_sizes, int n_in,
                              void* d_out, int out_size)
{
    const float *rgb=(const float*)d_in[0], *depth=(const float*)d_in[1], *lidar=(const float*)d_in[2];
    const float *prw=(const float*)d_in[3], *prb=(const float*)d_in[4], *pdw=(const float*)d_in[5], *pdb=(const float*)d_in[6];
    const float *plw=(const float*)d_in[7], *plb=(const float*)d_in[8];
    const float *aqw=(const float*)d_in[9], *aqb=(const float*)d_in[10], *akw=(const float*)d_in[11], *akb=(const float*)d_in[12];
    const float *avw=(const float*)d_in[13], *avb=(const float*)d_in[14], *aow=(const float*)d_in[15], *aob=(const float*)d_in[16];
    const float *sew1=(const float*)d_in[17], *seb1=(const float*)d_in[18], *sew2=(const float*)d_in[19], *seb2=(const float*)d_in[20];
    const float *gw=(const float*)d_in[21], *gb=(const float*)d_in[22], *fw=(const float*)d_in[23], *fb=(const float*)d_in[24];
    float* out = (float*)d_out;

    char* A = nullptr;
    cudaGetSymbolAddress((void**)&A, g_arena);
    size_t o = 0;
    auto al = [&](size_t bytes) { char* p = A + o; o += (bytes + 1023) & ~(size_t)1023; return p; };
    float* feat   = (float*)al(50331648);
    float* crossT = (float*)al(50331648);
    float* Y      = (float*)al(301989888);   // [3][4][1024][6144]
    float* spart  = (float*)al(50331648);    // [4][6][32][128][128]
    float* attnT  = (float*)al(12582912);    // [6*32][128][128]
    float* part   = (float*)al(1179648);
    float* inv    = (float*)al(49152);
    float* metric = (float*)al(49152);
    float* pool   = (float*)al(49152);
    float* se     = (float*)al(49152);
    float* gates  = (float*)al(49152);
    float* qkvb   = (float*)al(73728);       // [3][6144]
    float* obias  = (float*)al(12288);       // [3][1024]
    half* f_h    = (half*)al(25165824);      // [3][4][1024][1024]
    half* atc    = (half*)al(50331648);      // [3][4][1024][2048]
    half* fu_h   = (half*)al(25165824);      // [4][1024][3072]
    half* wqkvc  = (half*)al(37748736);      // [3][6144][1024]
    half* woc    = (half*)al(12582912);      // [3][1024][2048]
    half* wf_h   = (half*)al(18874368);      // [3072][3072]

    split_attn_w<<<73728, 256>>>(aqw, akw, avw, wqkvc);
    split_o_w<<<24576, 256>>>(aow, woc);
    cvt_w<<<36864, 256>>>(fw, wf_h);
    bias_qkv<<<72, 256>>>(aqb, akb, avb, qkvb);
    bias_o<<<12, 256>>>(aob, obias);

    gemm128<<<dim3(8,8,4), 256>>>(prw, rgb,   prb, feat,           512, 524288);
    gemm128<<<dim3(8,8,4), 256>>>(pdw, depth, pdb, feat + 4194304, 256, 262144);
    gemm128<<<dim3(8,8,4), 256>>>(plw, lidar, plb, feat + 8388608,  64, 65536);

    colreduce<<<dim3(16,8,3), 256>>>(feat, part);
    finalize_stats<<<dim3(16,3), 256>>>(part, inv, metric);
    trans_norm_split<<<dim3(32,32,12), 256>>>(feat, inv, crossT, f_h);

    for (int m = 0; m < 3; m++)
        hmma_gemm<<<dim3(48,8,4), 256, HG_SMEM>>>(f_h + (long long)m * 4194304, 1048576, 1024,
            wqkvc + (long long)m * 6291456, qkvb + m * 6144,
            Y + (long long)m * 25165824, 6291456, 6144, 1024, 0);

    scores_v3<<<dim3(4,6,32), 256>>>(Y, spart);
    softmax_v3<<<dim3(128,192), 128>>>(spart, attnT);
    av_v3<<<dim3(8,6,32), 256>>>(Y, attnT, atc);

    for (int m = 0; m < 3; m++)
        hmma_gemm<<<dim3(8,8,4), 256, HG_SMEM>>>(atc + (long long)m * 8388608, 2097152, 2048,
            woc + (long long)m * 2097152, obias + m * 1024,
            crossT + (long long)m * 4194304, 1048576, 1024, 2048, 1);

    se_pool_v2<<<dim3(8,12), 128>>>(crossT, pool);
    se_mlp<<<12, 256>>>(pool, sew1, seb1, sew2, seb2, se);
    gate_v2<<<4096, 128>>>(crossT, se, metric, gw, gb, gates);
    fuse_conv<<<49152, 256>>>(crossT, se, gates, fu_h);
    hmma_gemm<<<dim3(24,8,4), 256, HG_SMEM>>>(fu_h, 3145728, 3072, wf_h, fb, out, 3145728, 1024, 3072, 2);
}